// round 9
// baseline (speedup 1.0000x reference)
#include <cuda_runtime.h>
#include <math.h>

#define B_ 64
#define S_ 64
#define T_ 64
#define H_ 1024
#define E_ 1024
#define G_ 3072        // 3*H
#define V_ 32000
#define KC 32          // K-chunk for gru gemm passes

// ---------------- scratch (device globals; no runtime allocation) -------------
__device__ float g_gi0[S_ * B_ * G_];          // precomputed gi for layer 0, [step][b][3H] (48 MB, reused enc->dec)
__device__ float g_h[2][2][B_ * H_];           // hidden state [layer][parity][b*H+j]
__device__ float g_xl[B_ * H_];                // layer-0 output (input to layer 1) for current step
__device__ float g_top[(T_ - 1) * B_ * H_];    // decoder top-layer outputs, [s][b][H]

__device__ __forceinline__ float sigm(float x) { return 1.0f / (1.0f + expf(-x)); }

// ---------------- init: zero h(parity 0) and out[:,0,:] -----------------------
__global__ void init_kernel(float* __restrict__ out) {
    const int idx = blockIdx.x * blockDim.x + threadIdx.x;
    const int stride = gridDim.x * blockDim.x;
    if (idx < B_ * H_) {
        g_h[0][0][idx] = 0.0f;
        g_h[1][0][idx] = 0.0f;
    }
    for (int i = idx; i < B_ * V_; i += stride) {
        const int b = i / V_;
        const int v = i - b * V_;
        out[(size_t)b * (T_ * V_) + v] = 0.0f;   // outputs[:,0,:] = 0
    }
}

// ---------------- layer-0 input projection (embedding gather GEMM) ------------
// g_gi0[t*B+b, n] = sum_k emb[tok[b,t], k] * W[n, k] + bias[n]
// grid: (G_/64, nsteps), block: 256. Tile 64 rows (all b) x 64 cols.
__global__ void __launch_bounds__(256) gi0_kernel(
    const int* __restrict__ tokens, int tok_ld,
    const float* __restrict__ emb,
    const float* __restrict__ W,
    const float* __restrict__ bias)
{
    __shared__ __align__(16) float As[16][68];
    __shared__ __align__(16) float Ws[16][68];
    __shared__ int toks[64];

    const int t   = blockIdx.y;
    const int n0  = blockIdx.x * 64;
    const int tid = threadIdx.x;

    if (tid < 64) toks[tid] = tokens[tid * tok_ld + t];   // tokens[b][t]
    __syncthreads();

    float acc[4][4];
#pragma unroll
    for (int i = 0; i < 4; i++)
#pragma unroll
        for (int j = 0; j < 4; j++) acc[i][j] = 0.0f;

    const int lr = tid >> 2;          // 0..63 (loader row)
    const int lk = (tid & 3) << 2;    // 0,4,8,12 (loader k offset)
    const int ty = tid >> 4;          // 0..15 (row group of 4)
    const int tx = tid & 15;          // 0..15 (col group of 4)

    const float* arow = emb + (size_t)toks[lr] * E_ + lk;
    const float* wrow = W + (size_t)(n0 + lr) * E_ + lk;

    for (int k0 = 0; k0 < E_; k0 += 16) {
        const float4 a = *(const float4*)(arow + k0);
        const float4 w = *(const float4*)(wrow + k0);
        As[lk + 0][lr] = a.x; As[lk + 1][lr] = a.y; As[lk + 2][lr] = a.z; As[lk + 3][lr] = a.w;
        Ws[lk + 0][lr] = w.x; Ws[lk + 1][lr] = w.y; Ws[lk + 2][lr] = w.z; Ws[lk + 3][lr] = w.w;
        __syncthreads();
#pragma unroll
        for (int kk = 0; kk < 16; kk++) {
            const float4 av = *(const float4*)&As[kk][ty << 2];
            const float4 wv = *(const float4*)&Ws[kk][tx << 2];
            acc[0][0] += av.x * wv.x; acc[0][1] += av.x * wv.y; acc[0][2] += av.x * wv.z; acc[0][3] += av.x * wv.w;
            acc[1][0] += av.y * wv.x; acc[1][1] += av.y * wv.y; acc[1][2] += av.y * wv.z; acc[1][3] += av.y * wv.w;
            acc[2][0] += av.z * wv.x; acc[2][1] += av.z * wv.y; acc[2][2] += av.z * wv.z; acc[2][3] += av.z * wv.w;
            acc[3][0] += av.w * wv.x; acc[3][1] += av.w * wv.y; acc[3][2] += av.w * wv.z; acc[3][3] += av.w * wv.w;
        }
        __syncthreads();
    }

#pragma unroll
    for (int i = 0; i < 4; i++) {
        const int b = (ty << 2) + i;
        float* dst = g_gi0 + ((size_t)t * B_ + b) * G_ + n0 + (tx << 2);
#pragma unroll
        for (int j = 0; j < 4; j++)
            dst[j] = acc[i][j] + bias[n0 + (tx << 2) + j];
    }
}

// ---------------- recurrent gemm pass: acc[gate][row] += A(64x1024) @ W rows ---
// CTA owns 8 hidden columns j0..j0+7 -> W rows {gate*H + j0 + cj}.
// block: 128 threads: cj = tid&7 (hidden col), rb = tid>>3 (4-row block).
__device__ __forceinline__ void gru_gemm_pass(
    const float* __restrict__ A,
    const float* __restrict__ W,
    int j0, float (&acc)[3][4],
    float (*As)[68], float (*Ws)[25])
{
    const int tid = threadIdx.x;
    const int cj  = tid & 7;
    const int rb  = tid >> 3;

    for (int k0 = 0; k0 < H_; k0 += KC) {
        // load A chunk 64x32 (512 float4, 4 per thread), transposed into As[k][r]
#pragma unroll
        for (int i = 0; i < 4; i++) {
            const int lin = tid + i * 128;
            const int r   = lin >> 3;
            const int kk  = (lin & 7) << 2;
            const float4 v = *(const float4*)(A + (size_t)r * H_ + k0 + kk);
            As[kk + 0][r] = v.x; As[kk + 1][r] = v.y; As[kk + 2][r] = v.z; As[kk + 3][r] = v.w;
        }
        // load W chunk: 24 rows x 32 k (192 float4)
        {
            int lin = tid;
            int g = lin >> 3, kk = (lin & 7) << 2;
            const float* src = W + ((size_t)(g >> 3) * H_ + j0 + (g & 7)) * H_ + k0 + kk;
            float4 v = *(const float4*)src;
            Ws[kk + 0][g] = v.x; Ws[kk + 1][g] = v.y; Ws[kk + 2][g] = v.z; Ws[kk + 3][g] = v.w;
            if (tid < 64) {
                lin = tid + 128;
                g = lin >> 3; kk = (lin & 7) << 2;
                src = W + ((size_t)(g >> 3) * H_ + j0 + (g & 7)) * H_ + k0 + kk;
                v = *(const float4*)src;
                Ws[kk + 0][g] = v.x; Ws[kk + 1][g] = v.y; Ws[kk + 2][g] = v.z; Ws[kk + 3][g] = v.w;
            }
        }
        __syncthreads();
#pragma unroll
        for (int kk = 0; kk < KC; kk++) {
            const float4 av = *(const float4*)&As[kk][rb << 2];
            const float wr = Ws[kk][cj];
            const float wz = Ws[kk][8 + cj];
            const float wn = Ws[kk][16 + cj];
            acc[0][0] += av.x * wr; acc[0][1] += av.y * wr; acc[0][2] += av.z * wr; acc[0][3] += av.w * wr;
            acc[1][0] += av.x * wz; acc[1][1] += av.y * wz; acc[1][2] += av.z * wz; acc[1][3] += av.w * wz;
            acc[2][0] += av.x * wn; acc[2][1] += av.y * wn; acc[2][2] += av.z * wn; acc[2][3] += av.w * wn;
        }
        __syncthreads();
    }
}

// ---------------- layer-0 step: gh = h0 @ Whh0^T, gi precomputed --------------
// grid: 128 CTAs (8 hidden cols each), block: 128
__global__ void __launch_bounds__(128) gru_l0_kernel(
    const float* __restrict__ Whh, const float* __restrict__ bhh,
    const int* __restrict__ lengths, int t, int parity)
{
    __shared__ __align__(16) float As[KC][68];
    __shared__ float Ws[KC][25];

    const int j0  = blockIdx.x * 8;
    const int tid = threadIdx.x;
    const int cj  = tid & 7;
    const int rb  = tid >> 3;

    const float* hread = g_h[0][parity];
    float acc[3][4];
#pragma unroll
    for (int g = 0; g < 3; g++)
#pragma unroll
        for (int i = 0; i < 4; i++) acc[g][i] = 0.0f;

    gru_gemm_pass(hread, Whh, j0, acc, As, Ws);

    const int j = j0 + cj;
    const float* gi = g_gi0 + (size_t)t * B_ * G_;
    float* hwrite = g_h[0][parity ^ 1];
    const float br = bhh[j], bz = bhh[H_ + j], bn = bhh[2 * H_ + j];

#pragma unroll
    for (int i = 0; i < 4; i++) {
        const int b = (rb << 2) + i;
        const float hprev = hread[b * H_ + j];
        const float gir = gi[(size_t)b * G_ + j];
        const float giz = gi[(size_t)b * G_ + H_ + j];
        const float gin = gi[(size_t)b * G_ + 2 * H_ + j];
        const float r = sigm(gir + acc[0][i] + br);
        const float z = sigm(giz + acc[1][i] + bz);
        const float n = tanhf(gin + r * (acc[2][i] + bn));
        const float hnew = (1.0f - z) * n + z * hprev;
        g_xl[b * H_ + j] = hnew;                       // layer-1 input (unmasked)
        float hs = hnew;
        if (lengths != nullptr && t >= lengths[b]) hs = hprev;   // packed-seq freeze
        hwrite[b * H_ + j] = hs;
    }
}

// ---------------- layer-1 step: gi = xl @ Wih1^T, gh = h1 @ Whh1^T ------------
__global__ void __launch_bounds__(128) gru_l1_kernel(
    const float* __restrict__ Wih, const float* __restrict__ Whh,
    const float* __restrict__ bih, const float* __restrict__ bhh,
    const int* __restrict__ lengths, int t, int parity, int store_top)
{
    __shared__ __align__(16) float As[KC][68];
    __shared__ float Ws[KC][25];

    const int j0  = blockIdx.x * 8;
    const int tid = threadIdx.x;
    const int cj  = tid & 7;
    const int rb  = tid >> 3;

    const float* hread = g_h[1][parity];

    float gia[3][4], gha[3][4];
#pragma unroll
    for (int g = 0; g < 3; g++)
#pragma unroll
        for (int i = 0; i < 4; i++) { gia[g][i] = 0.0f; gha[g][i] = 0.0f; }

    gru_gemm_pass(g_xl,  Wih, j0, gia, As, Ws);
    gru_gemm_pass(hread, Whh, j0, gha, As, Ws);

    const int j = j0 + cj;
    float* hwrite = g_h[1][parity ^ 1];
    const float bir = bih[j], biz = bih[H_ + j], bin = bih[2 * H_ + j];
    const float bhr = bhh[j], bhz = bhh[H_ + j], bhn = bhh[2 * H_ + j];

#pragma unroll
    for (int i = 0; i < 4; i++) {
        const int b = (rb << 2) + i;
        const float hprev = hread[b * H_ + j];
        const float r = sigm((gia[0][i] + bir) + (gha[0][i] + bhr));
        const float z = sigm((gia[1][i] + biz) + (gha[1][i] + bhz));
        const float n = tanhf((gia[2][i] + bin) + r * (gha[2][i] + bhn));
        const float hnew = (1.0f - z) * n + z * hprev;
        if (store_top) g_top[((size_t)t * B_ + b) * H_ + j] = hnew;
        float hs = hnew;
        if (lengths != nullptr && t >= lengths[b]) hs = hprev;
        hwrite[b * H_ + j] = hs;
    }
}

// ---------------- output GEMM: out[b, s+1, v] = g_top[s,b,:] @ Wout[v,:] + bout
// grid: (V_/64, T_-1), block: 256
__global__ void __launch_bounds__(256) out_gemm_kernel(
    const float* __restrict__ W, const float* __restrict__ bias,
    float* __restrict__ out)
{
    __shared__ __align__(16) float As[16][68];
    __shared__ __align__(16) float Ws[16][68];

    const int s   = blockIdx.y;
    const int n0  = blockIdx.x * 64;
    const int tid = threadIdx.x;

    float acc[4][4];
#pragma unroll
    for (int i = 0; i < 4; i++)
#pragma unroll
        for (int j = 0; j < 4; j++) acc[i][j] = 0.0f;

    const int lr = tid >> 2;
    const int lk = (tid & 3) << 2;
    const int ty = tid >> 4;
    const int tx = tid & 15;

    const float* arow = g_top + ((size_t)s * B_ + lr) * H_ + lk;
    const float* wrow = W + (size_t)(n0 + lr) * H_ + lk;

    for (int k0 = 0; k0 < H_; k0 += 16) {
        const float4 a = *(const float4*)(arow + k0);
        const float4 w = *(const float4*)(wrow + k0);
        As[lk + 0][lr] = a.x; As[lk + 1][lr] = a.y; As[lk + 2][lr] = a.z; As[lk + 3][lr] = a.w;
        Ws[lk + 0][lr] = w.x; Ws[lk + 1][lr] = w.y; Ws[lk + 2][lr] = w.z; Ws[lk + 3][lr] = w.w;
        __syncthreads();
#pragma unroll
        for (int kk = 0; kk < 16; kk++) {
            const float4 av = *(const float4*)&As[kk][ty << 2];
            const float4 wv = *(const float4*)&Ws[kk][tx << 2];
            acc[0][0] += av.x * wv.x; acc[0][1] += av.x * wv.y; acc[0][2] += av.x * wv.z; acc[0][3] += av.x * wv.w;
            acc[1][0] += av.y * wv.x; acc[1][1] += av.y * wv.y; acc[1][2] += av.y * wv.z; acc[1][3] += av.y * wv.w;
            acc[2][0] += av.z * wv.x; acc[2][1] += av.z * wv.y; acc[2][2] += av.z * wv.z; acc[2][3] += av.z * wv.w;
            acc[3][0] += av.w * wv.x; acc[3][1] += av.w * wv.y; acc[3][2] += av.w * wv.z; acc[3][3] += av.w * wv.w;
        }
        __syncthreads();
    }

#pragma unroll
    for (int i = 0; i < 4; i++) {
        const int b = (ty << 2) + i;
        float* dst = out + (size_t)b * (T_ * V_) + (size_t)(s + 1) * V_ + n0 + (tx << 2);
#pragma unroll
        for (int j = 0; j < 4; j++)
            dst[j] = acc[i][j] + bias[n0 + (tx << 2) + j];
    }
}

// ------------------------------- host driver ----------------------------------
extern "C" void kernel_launch(void* const* d_in, const int* in_sizes, int n_in,
                              void* d_out, int out_size) {
    (void)in_sizes; (void)n_in; (void)out_size;

    const int*   src_tokens  = (const int*)d_in[0];
    const int*   src_lengths = (const int*)d_in[1];
    const int*   trg         = (const int*)d_in[2];
    const float* emb_enc = (const float*)d_in[3];
    const float* Wih_enc = (const float*)d_in[4];
    const float* Whh_enc = (const float*)d_in[5];
    const float* bih_enc = (const float*)d_in[6];
    const float* bhh_enc = (const float*)d_in[7];
    const float* emb_dec = (const float*)d_in[8];
    const float* Wih_dec = (const float*)d_in[9];
    const float* Whh_dec = (const float*)d_in[10];
    const float* bih_dec = (const float*)d_in[11];
    const float* bhh_dec = (const float*)d_in[12];
    const float* Wout    = (const float*)d_in[13];
    const float* bout    = (const float*)d_in[14];
    float* out = (float*)d_out;

    const size_t LW = (size_t)G_ * H_;   // per-layer weight stride (3H x 1024)
    const size_t LB = (size_t)G_;        // per-layer bias stride

    // 1) init: zero h state (parity 0) + zero out[:,0,:]
    init_kernel<<<512, 256>>>(out);

    // 2) encoder layer-0 input projection for all S steps
    gi0_kernel<<<dim3(G_ / 64, S_), 256>>>(src_tokens, S_, emb_enc, Wih_enc, bih_enc);

    // 3) encoder recurrence
    for (int t = 0; t < S_; t++) {
        const int p = t & 1;
        gru_l0_kernel<<<H_ / 8, 128>>>(Whh_enc, bhh_enc, src_lengths, t, p);
        gru_l1_kernel<<<H_ / 8, 128>>>(Wih_enc + LW, Whh_enc + LW,
                                       bih_enc + LB, bhh_enc + LB,
                                       src_lengths, t, p, 0);
    }

    // 4) decoder layer-0 input projection (tokens trg[:, 0..T-2])
    gi0_kernel<<<dim3(G_ / 64, T_ - 1), 256>>>(trg, T_, emb_dec, Wih_dec, bih_dec);

    // 5) decoder recurrence (continues parity: encoder ran S_=64 steps, even)
    for (int s = 0; s < T_ - 1; s++) {
        const int p = s & 1;
        gru_l0_kernel<<<H_ / 8, 128>>>(Whh_dec, bhh_dec, nullptr, s, p);
        gru_l1_kernel<<<H_ / 8, 128>>>(Wih_dec + LW, Whh_dec + LW,
                                       bih_dec + LB, bhh_dec + LB,
                                       nullptr, s, p, 1);
    }

    // 6) vocab projection for all steps at once
    out_gemm_kernel<<<dim3(V_ / 64, T_ - 1), 256>>>(Wout, bout, out);
}

// round 10
// speedup vs baseline: 1.9000x; 1.9000x over previous
#include <cuda_runtime.h>
#include <cuda_bf16.h>
#include <math.h>

#define B_ 64
#define S_ 64
#define T_ 64
#define H_ 1024
#define E_ 1024
#define G_ 3072
#define V_ 32000
#define ASTR 36   // smem row stride (u32 words) for gru tiles (32 data + 4 pad)
#define AST2 20   // smem row stride for big tiles (16 data + 4 pad)

typedef __nv_bfloat16 bf16;

// ---------------- device-global scratch ----------------
__device__ bf16 g_wr_hi[6ull * G_ * H_];      // 0:Whh_e0 1:Whh_e1 2:Wih_e1 3:Whh_d0 4:Whh_d1 5:Wih_d1
__device__ bf16 g_wr_lo[6ull * G_ * H_];
__device__ bf16 g_wi0_hi[2ull * G_ * H_];     // layer-0 Wih: enc, dec
__device__ bf16 g_wi0_lo[2ull * G_ * H_];
__device__ bf16 g_wout_hi[(size_t)V_ * H_];
__device__ bf16 g_wout_lo[(size_t)V_ * H_];
__device__ bf16 g_x0_hi[(size_t)S_ * B_ * E_];   // per-phase embedded inputs
__device__ bf16 g_x0_lo[(size_t)S_ * B_ * E_];
__device__ float g_gi0[(size_t)S_ * B_ * G_];    // layer-0 input preacts (+bih)
__device__ float g_hf[2][2][B_ * H_];            // fp32 h [layer][parity]
__device__ bf16 g_h_hi[2][2][B_ * H_];
__device__ bf16 g_h_lo[2][2][B_ * H_];
__device__ bf16 g_xl_hi[B_ * H_];
__device__ bf16 g_xl_lo[B_ * H_];
__device__ bf16 g_top_hi[(size_t)(T_ - 1) * B_ * H_];
__device__ bf16 g_top_lo[(size_t)(T_ - 1) * B_ * H_];

__device__ __forceinline__ float sigm(float x) { return 1.0f / (1.0f + expf(-x)); }

__device__ __forceinline__ void split2(float x, bf16& hi, bf16& lo) {
    hi = __float2bfloat16(x);
    lo = __float2bfloat16(x - __bfloat162float(hi));
}

__device__ __forceinline__ void mma_acc(float (&d)[4],
    unsigned a0, unsigned a1, unsigned a2, unsigned a3, unsigned b0, unsigned b1)
{
    asm volatile(
        "mma.sync.aligned.m16n8k16.row.col.f32.bf16.bf16.f32 "
        "{%0,%1,%2,%3},{%4,%5,%6,%7},{%8,%9},{%0,%1,%2,%3};\n"
        : "+f"(d[0]), "+f"(d[1]), "+f"(d[2]), "+f"(d[3])
        : "r"(a0), "r"(a1), "r"(a2), "r"(a3), "r"(b0), "r"(b1));
}

// ---------------- init ----------------
__global__ void init_kernel(float* __restrict__ out) {
    const int idx = blockIdx.x * blockDim.x + threadIdx.x;
    const int stride = gridDim.x * blockDim.x;
    const bf16 z = __float2bfloat16(0.0f);
    for (int i = idx; i < B_ * H_; i += stride) {
        g_hf[0][0][i] = 0.0f; g_hf[1][0][i] = 0.0f;
        g_h_hi[0][0][i] = z; g_h_lo[0][0][i] = z;
        g_h_hi[1][0][i] = z; g_h_lo[1][0][i] = z;
    }
    for (int i = idx; i < B_ * V_; i += stride) {
        const int b = i / V_;
        const int v = i - b * V_;
        out[(size_t)b * (T_ * V_) + v] = 0.0f;
    }
}

// ---------------- fp32 -> bf16 hi/lo weight split ----------------
__global__ void split_kernel(const float* __restrict__ src, int sel, size_t off, size_t n) {
    bf16 *hi, *lo;
    if (sel == 0)      { hi = g_wr_hi + off;  lo = g_wr_lo + off; }
    else if (sel == 1) { hi = g_wi0_hi + off; lo = g_wi0_lo + off; }
    else               { hi = g_wout_hi + off; lo = g_wout_lo + off; }
    size_t i = (size_t)blockIdx.x * blockDim.x + threadIdx.x;
    const size_t stride = (size_t)gridDim.x * blockDim.x;
    for (; i < n; i += stride) {
        bf16 h, l; split2(src[i], h, l);
        hi[i] = h; lo[i] = l;
    }
}

// ---------------- embedding gather + split (one phase) ----------------
__global__ void gather_x0(const int* __restrict__ tokens, int tld,
                          const float* __restrict__ emb, int nsteps)
{
    const int total = nsteps * B_ * (E_ / 4);
    int idx = blockIdx.x * blockDim.x + threadIdx.x;
    const int stride = gridDim.x * blockDim.x;
    for (; idx < total; idx += stride) {
        const int q = idx & 255;        // float4 within row
        const int rb = idx >> 8;        // step*64 + b
        const int b = rb & 63;
        const int st = rb >> 6;
        const int tok = tokens[b * tld + st];
        const float4 v = ((const float4*)(emb + (size_t)tok * E_))[q];
        bf16 h, l;
        const size_t base = (size_t)rb * E_ + q * 4;
        split2(v.x, h, l); g_x0_hi[base + 0] = h; g_x0_lo[base + 0] = l;
        split2(v.y, h, l); g_x0_hi[base + 1] = h; g_x0_lo[base + 1] = l;
        split2(v.z, h, l); g_x0_hi[base + 2] = h; g_x0_lo[base + 2] = l;
        split2(v.w, h, l); g_x0_hi[base + 3] = h; g_x0_lo[base + 3] = l;
    }
}

// ================= big batched MMA GEMM: 64 x 128 tile, 256 thr ==============
__device__ __forceinline__ void big_tile_mainloop(
    const bf16* __restrict__ Ahi, const bf16* __restrict__ Alo,
    const bf16* __restrict__ Bhi, const bf16* __restrict__ Blo,
    int n0, unsigned (*sA)[64 * AST2], unsigned (*sB)[128 * AST2],
    float (&acc)[8][4], int tid, int mt, int nh, int g, int c)
{
    for (int k0 = 0; k0 < H_; k0 += 32) {
#pragma unroll
        for (int it = 0; it < 2; it++) {              // A: 512 int4
            const int idx = tid + it * 256;
            const int pl = idx >> 8;
            const int r = (idx >> 2) & 63;
            const int q = idx & 3;
            *(int4*)&sA[pl][r * AST2 + q * 4] =
                *(const int4*)((pl ? Alo : Ahi) + (size_t)r * H_ + k0 + q * 8);
        }
#pragma unroll
        for (int it = 0; it < 4; it++) {              // B: 1024 int4
            const int idx = tid + it * 256;
            const int pl = idx >> 9;
            const int i = idx & 511;
            const int r = i >> 2;
            const int q = i & 3;
            *(int4*)&sB[pl][r * AST2 + q * 4] =
                *(const int4*)((pl ? Blo : Bhi) + (size_t)(n0 + r) * H_ + k0 + q * 8);
        }
        __syncthreads();
#pragma unroll
        for (int ks = 0; ks < 2; ks++) {
            const int kw = ks * 8;
            const int ar = (mt * 16 + g) * AST2 + kw + c;
            const unsigned ah0 = sA[0][ar],            ah1 = sA[0][ar + 8 * AST2];
            const unsigned ah2 = sA[0][ar + 4],        ah3 = sA[0][ar + 8 * AST2 + 4];
            const unsigned al0 = sA[1][ar],            al1 = sA[1][ar + 8 * AST2];
            const unsigned al2 = sA[1][ar + 4],        al3 = sA[1][ar + 8 * AST2 + 4];
#pragma unroll
            for (int nt = 0; nt < 8; nt++) {
                const int br = (nh * 64 + nt * 8 + g) * AST2 + kw + c;
                const unsigned bh0 = sB[0][br], bh1 = sB[0][br + 4];
                const unsigned bl0 = sB[1][br], bl1 = sB[1][br + 4];
                mma_acc(acc[nt], ah0, ah1, ah2, ah3, bh0, bh1);
                mma_acc(acc[nt], ah0, ah1, ah2, ah3, bl0, bl1);
                mma_acc(acc[nt], al0, al1, al2, al3, bh0, bh1);
            }
        }
        __syncthreads();
    }
}

// ---- layer-0 input projection, all steps of one phase: gi0 = X0 @ W^T + bih --
__global__ void __launch_bounds__(256) gi0_mma(const float* __restrict__ bias, size_t woff)
{
    __shared__ unsigned sA[2][64 * AST2];
    __shared__ unsigned sB[2][128 * AST2];
    const int sidx = blockIdx.x;
    const int n0 = blockIdx.y * 128;
    const int tid = threadIdx.x, w = tid >> 5, lane = tid & 31;
    const int mt = w & 3, nh = w >> 2, g = lane >> 2, c = lane & 3;

    float acc[8][4];
#pragma unroll
    for (int i = 0; i < 8; i++)
#pragma unroll
        for (int j = 0; j < 4; j++) acc[i][j] = 0.0f;

    big_tile_mainloop(g_x0_hi + (size_t)sidx * B_ * E_, g_x0_lo + (size_t)sidx * B_ * E_,
                      g_wi0_hi + woff, g_wi0_lo + woff, n0, sA, sB, acc, tid, mt, nh, g, c);

#pragma unroll
    for (int nt = 0; nt < 8; nt++) {
        const int v = n0 + nh * 64 + nt * 8 + 2 * c;
        const float b0 = bias[v], b1 = bias[v + 1];
#pragma unroll
        for (int hh = 0; hh < 2; hh++) {
            const int b = mt * 16 + g + hh * 8;
            float2 r;
            r.x = acc[nt][hh * 2 + 0] + b0;
            r.y = acc[nt][hh * 2 + 1] + b1;
            *(float2*)&g_gi0[((size_t)sidx * B_ + b) * G_ + v] = r;
        }
    }
}

// ---- vocab projection: out[b, s+1, v] = top[s,b,:] @ Wout^T + bout ----------
__global__ void __launch_bounds__(256) out_mma(const float* __restrict__ bout,
                                               float* __restrict__ out)
{
    __shared__ unsigned sA[2][64 * AST2];
    __shared__ unsigned sB[2][128 * AST2];
    const int s = blockIdx.x;
    const int n0 = blockIdx.y * 128;
    const int tid = threadIdx.x, w = tid >> 5, lane = tid & 31;
    const int mt = w & 3, nh = w >> 2, g = lane >> 2, c = lane & 3;

    float acc[8][4];
#pragma unroll
    for (int i = 0; i < 8; i++)
#pragma unroll
        for (int j = 0; j < 4; j++) acc[i][j] = 0.0f;

    big_tile_mainloop(g_top_hi + (size_t)s * B_ * H_, g_top_lo + (size_t)s * B_ * H_,
                      g_wout_hi, g_wout_lo, n0, sA, sB, acc, tid, mt, nh, g, c);

#pragma unroll
    for (int nt = 0; nt < 8; nt++) {
        const int v = n0 + nh * 64 + nt * 8 + 2 * c;
        const float b0 = __ldg(bout + v), b1 = __ldg(bout + v + 1);
#pragma unroll
        for (int hh = 0; hh < 2; hh++) {
            const int b = mt * 16 + g + hh * 8;
            float2 r;
            r.x = acc[nt][hh * 2 + 0] + b0;
            r.y = acc[nt][hh * 2 + 1] + b1;
            *(float2*)&out[(size_t)b * (T_ * V_) + (size_t)(s + 1) * V_ + v] = r;
        }
    }
}

// ================= recurrent step kernels: 64 x 24 tile, 128 thr =============
// warp w owns m-strip w*16; 3 n-frags = 3 gates x 8 hidden cols (j0..j0+7)
__device__ __forceinline__ void gru_pass(
    const bf16* __restrict__ Ahi, const bf16* __restrict__ Alo,
    const bf16* __restrict__ Whi, const bf16* __restrict__ Wlo,
    int j0, unsigned (*sA)[64 * ASTR], unsigned (*sW)[24 * ASTR],
    float (&acc)[3][4], int tid, int m0, int g, int c)
{
    for (int k0 = 0; k0 < H_; k0 += 64) {
#pragma unroll
        for (int it = 0; it < 8; it++) {              // A: 1024 int4 (2 planes)
            const int idx = tid + it * 128;
            const int pl = idx >> 9;
            const int rem = idx & 511;
            const int r = rem >> 3, q = rem & 7;
            *(int4*)&sA[pl][r * ASTR + q * 4] =
                *(const int4*)((pl ? Alo : Ahi) + (size_t)r * H_ + k0 + q * 8);
        }
#pragma unroll
        for (int it = 0; it < 3; it++) {              // W: 384 int4 (2 planes)
            const int idx = tid + it * 128;
            const int pl = (idx >= 192) ? 1 : 0;
            const int i = idx - 192 * pl;
            const int r = i >> 3, q = i & 7;
            const int grow = (r >> 3) * H_ + j0 + (r & 7);
            *(int4*)&sW[pl][r * ASTR + q * 4] =
                *(const int4*)((pl ? Wlo : Whi) + (size_t)grow * H_ + k0 + q * 8);
        }
        __syncthreads();
#pragma unroll
        for (int ks = 0; ks < 4; ks++) {
            const int kw = ks * 8;
            const int ar = (m0 + g) * ASTR + kw + c;
            const unsigned ah0 = sA[0][ar],     ah1 = sA[0][ar + 8 * ASTR];
            const unsigned ah2 = sA[0][ar + 4], ah3 = sA[0][ar + 8 * ASTR + 4];
            const unsigned al0 = sA[1][ar],     al1 = sA[1][ar + 8 * ASTR];
            const unsigned al2 = sA[1][ar + 4], al3 = sA[1][ar + 8 * ASTR + 4];
            unsigned bh0[3], bh1[3], bl0[3], bl1[3];
#pragma unroll
            for (int nt = 0; nt < 3; nt++) {
                const int wr = (nt * 8 + g) * ASTR + kw + c;
                bh0[nt] = sW[0][wr]; bh1[nt] = sW[0][wr + 4];
                bl0[nt] = sW[1][wr]; bl1[nt] = sW[1][wr + 4];
            }
#pragma unroll
            for (int nt = 0; nt < 3; nt++) mma_acc(acc[nt], ah0, ah1, ah2, ah3, bh0[nt], bh1[nt]);
#pragma unroll
            for (int nt = 0; nt < 3; nt++) mma_acc(acc[nt], ah0, ah1, ah2, ah3, bl0[nt], bl1[nt]);
#pragma unroll
            for (int nt = 0; nt < 3; nt++) mma_acc(acc[nt], al0, al1, al2, al3, bh0[nt], bh1[nt]);
        }
        __syncthreads();
    }
}

__device__ __forceinline__ void dump_acc(float* C, float (&acc)[3][4], int m0, int g, int c) {
#pragma unroll
    for (int nt = 0; nt < 3; nt++) {
        const int col = nt * 8 + 2 * c;
        C[(m0 + g) * 25 + col]         = acc[nt][0];
        C[(m0 + g) * 25 + col + 1]     = acc[nt][1];
        C[(m0 + g + 8) * 25 + col]     = acc[nt][2];
        C[(m0 + g + 8) * 25 + col + 1] = acc[nt][3];
    }
}

// ---- layer-0 step: gh = h0 @ Whh0^T; gi precomputed in g_gi0 ----------------
__global__ void __launch_bounds__(128) gru_l0(
    size_t woff, const float* __restrict__ bhh,
    const int* __restrict__ lengths, int t_state, int t_gi, int par)
{
    __shared__ unsigned sA[2][64 * ASTR];
    __shared__ unsigned sW[2][24 * ASTR];
    __shared__ float C[64 * 25];
    const int tid = threadIdx.x, w = tid >> 5, lane = tid & 31;
    const int g = lane >> 2, c = lane & 3, m0 = w * 16;
    const int j0 = blockIdx.x * 8;

    float acc[3][4];
#pragma unroll
    for (int i = 0; i < 3; i++)
#pragma unroll
        for (int j = 0; j < 4; j++) acc[i][j] = 0.0f;

    gru_pass(g_h_hi[0][par], g_h_lo[0][par], g_wr_hi + woff, g_wr_lo + woff,
             j0, sA, sW, acc, tid, m0, g, c);
    dump_acc(C, acc, m0, g, c);
    __syncthreads();

    const float* hf = g_hf[0][par];
    float* hfn = g_hf[0][par ^ 1];
#pragma unroll
    for (int p = 0; p < 4; p++) {
        const int idx = tid + p * 128;
        const int b = idx >> 3, jj = idx & 7;
        const int j = j0 + jj;
        const size_t gb = ((size_t)t_gi * B_ + b) * G_;
        const float r = sigm(g_gi0[gb + j] + C[b * 25 + jj] + bhh[j]);
        const float z = sigm(g_gi0[gb + H_ + j] + C[b * 25 + 8 + jj] + bhh[H_ + j]);
        const float n = tanhf(g_gi0[gb + 2 * H_ + j] + r * (C[b * 25 + 16 + jj] + bhh[2 * H_ + j]));
        const float hprev = hf[b * H_ + j];
        const float hnew = (1.0f - z) * n + z * hprev;
        bf16 xh, xl; split2(hnew, xh, xl);
        g_xl_hi[b * H_ + j] = xh; g_xl_lo[b * H_ + j] = xl;
        float hs = hnew;
        if (lengths && t_state >= lengths[b]) hs = hprev;
        hfn[b * H_ + j] = hs;
        bf16 sh, sl; split2(hs, sh, sl);
        g_h_hi[0][par ^ 1][b * H_ + j] = sh;
        g_h_lo[0][par ^ 1][b * H_ + j] = sl;
    }
}

// ---- layer-1 step: gi = xl @ Wih1^T, gh = h1 @ Whh1^T -----------------------
__global__ void __launch_bounds__(128) gru_l1(
    size_t woffi, size_t woffh,
    const float* __restrict__ bih, const float* __restrict__ bhh,
    const int* __restrict__ lengths, int t_state, int par, int store_top, int step)
{
    __shared__ unsigned sA[2][64 * ASTR];
    __shared__ unsigned sW[2][24 * ASTR];
    __shared__ float C1[64 * 25];
    __shared__ float C2[64 * 25];
    const int tid = threadIdx.x, w = tid >> 5, lane = tid & 31;
    const int g = lane >> 2, c = lane & 3, m0 = w * 16;
    const int j0 = blockIdx.x * 8;

    float acc[3][4];
#pragma unroll
    for (int i = 0; i < 3; i++)
#pragma unroll
        for (int j = 0; j < 4; j++) acc[i][j] = 0.0f;
    gru_pass(g_xl_hi, g_xl_lo, g_wr_hi + woffi, g_wr_lo + woffi,
             j0, sA, sW, acc, tid, m0, g, c);
    dump_acc(C1, acc, m0, g, c);

#pragma unroll
    for (int i = 0; i < 3; i++)
#pragma unroll
        for (int j = 0; j < 4; j++) acc[i][j] = 0.0f;
    gru_pass(g_h_hi[1][par], g_h_lo[1][par], g_wr_hi + woffh, g_wr_lo + woffh,
             j0, sA, sW, acc, tid, m0, g, c);
    dump_acc(C2, acc, m0, g, c);
    __syncthreads();

    const float* hf = g_hf[1][par];
    float* hfn = g_hf[1][par ^ 1];
#pragma unroll
    for (int p = 0; p < 4; p++) {
        const int idx = tid + p * 128;
        const int b = idx >> 3, jj = idx & 7;
        const int j = j0 + jj;
        const float r = sigm(C1[b * 25 + jj] + bih[j] + C2[b * 25 + jj] + bhh[j]);
        const float z = sigm(C1[b * 25 + 8 + jj] + bih[H_ + j] + C2[b * 25 + 8 + jj] + bhh[H_ + j]);
        const float n = tanhf(C1[b * 25 + 16 + jj] + bih[2 * H_ + j]
                              + r * (C2[b * 25 + 16 + jj] + bhh[2 * H_ + j]));
        const float hprev = hf[b * H_ + j];
        const float hnew = (1.0f - z) * n + z * hprev;
        if (store_top) {
            bf16 th, tl; split2(hnew, th, tl);
            g_top_hi[((size_t)step * B_ + b) * H_ + j] = th;
            g_top_lo[((size_t)step * B_ + b) * H_ + j] = tl;
        }
        float hs = hnew;
        if (lengths && t_state >= lengths[b]) hs = hprev;
        hfn[b * H_ + j] = hs;
        bf16 sh, sl; split2(hs, sh, sl);
        g_h_hi[1][par ^ 1][b * H_ + j] = sh;
        g_h_lo[1][par ^ 1][b * H_ + j] = sl;
    }
}

// ------------------------------- host driver ---------------------------------
extern "C" void kernel_launch(void* const* d_in, const int* in_sizes, int n_in,
                              void* d_out, int out_size) {
    (void)in_sizes; (void)n_in; (void)out_size;
    const int*   src_tokens  = (const int*)d_in[0];
    const int*   src_lengths = (const int*)d_in[1];
    const int*   trg         = (const int*)d_in[2];
    const float* emb_enc = (const float*)d_in[3];
    const float* Wih_enc = (const float*)d_in[4];
    const float* Whh_enc = (const float*)d_in[5];
    const float* bih_enc = (const float*)d_in[6];
    const float* bhh_enc = (const float*)d_in[7];
    const float* emb_dec = (const float*)d_in[8];
    const float* Wih_dec = (const float*)d_in[9];
    const float* Whh_dec = (const float*)d_in[10];
    const float* bih_dec = (const float*)d_in[11];
    const float* bhh_dec = (const float*)d_in[12];
    const float* Wout    = (const float*)d_in[13];
    const float* bout    = (const float*)d_in[14];
    float* out = (float*)d_out;

    const size_t GH = (size_t)G_ * H_;

    init_kernel<<<512, 256>>>(out);

    // weight splits
    split_kernel<<<2048, 256>>>(Whh_enc,      0, 0 * GH, GH);
    split_kernel<<<2048, 256>>>(Whh_enc + GH, 0, 1 * GH, GH);
    split_kernel<<<2048, 256>>>(Wih_enc + GH, 0, 2 * GH, GH);
    split_kernel<<<2048, 256>>>(Whh_dec,      0, 3 * GH, GH);
    split_kernel<<<2048, 256>>>(Whh_dec + GH, 0, 4 * GH, GH);
    split_kernel<<<2048, 256>>>(Wih_dec + GH, 0, 5 * GH, GH);
    split_kernel<<<2048, 256>>>(Wih_enc, 1, 0,  GH);
    split_kernel<<<2048, 256>>>(Wih_dec, 1, GH, GH);
    split_kernel<<<2048, 256>>>(Wout,    2, 0,  (size_t)V_ * H_);

    // encoder: batched layer-0 input projection, then recurrence
    gather_x0<<<2048, 256>>>(src_tokens, S_, emb_enc, S_);
    gi0_mma<<<dim3(S_, G_ / 128), 256>>>(bih_enc, 0);
    for (int t = 0; t < S_; t++) {
        const int p = t & 1;
        gru_l0<<<H_ / 8, 128>>>(0 * GH, bhh_enc, src_lengths, t, t, p);
        gru_l1<<<H_ / 8, 128>>>(2 * GH, 1 * GH, bih_enc + G_, bhh_enc + G_,
                                src_lengths, t, p, 0, 0);
    }

    // decoder
    gather_x0<<<2048, 256>>>(trg, T_, emb_dec, T_ - 1);
    gi0_mma<<<dim3(T_ - 1, G_ / 128), 256>>>(bih_dec, GH);
    for (int s = 0; s < T_ - 1; s++) {
        const int p = s & 1;
        gru_l0<<<H_ / 8, 128>>>(3 * GH, bhh_dec, nullptr, s, s, p);
        gru_l1<<<H_ / 8, 128>>>(5 * GH, 4 * GH, bih_dec + G_, bhh_dec + G_,
                                nullptr, s, p, 1, s);
    }

    // vocab projection (s innermost in grid.x -> Wout tile shared through L2)
    out_mma<<<dim3(T_ - 1, V_ / 128), 256>>>(bout, out);
}

// round 11
// speedup vs baseline: 2.8090x; 1.4784x over previous
#include <cuda_runtime.h>
#include <cuda_bf16.h>
#include <math.h>

#define B_ 64
#define S_ 64
#define T_ 64
#define H_ 1024
#define E_ 1024
#define G_ 3072
#define V_ 32000
#define NSTEP 127
#define ASTR 36                      // gru smem row stride (u32)
#define AST2 20                      // big-tile smem row stride (u32)
#define SA_SZ (64 * ASTR)
#define SW_SZ (24 * ASTR)
#define GRU_SMEM_WORDS (4 * SA_SZ + 4 * SW_SZ + 1600)
#define GRU_SMEM_BYTES (GRU_SMEM_WORDS * 4)
#define GH_ ((size_t)G_ * H_)

typedef __nv_bfloat16 bf16;

// ---------------- device-global scratch ----------------
__device__ bf16 g_wr_hi[6ull * G_ * H_];   // 0:Whh_e0 1:Whh_e1 2:Wih_e1 3:Whh_d0 4:Whh_d1 5:Wih_d1
__device__ bf16 g_wr_lo[6ull * G_ * H_];
__device__ bf16 g_wi0_hi[2ull * G_ * H_];  // layer-0 Wih: enc, dec
__device__ bf16 g_wi0_lo[2ull * G_ * H_];
__device__ bf16 g_wout_hi[(size_t)V_ * H_];
__device__ bf16 g_wout_lo[(size_t)V_ * H_];
__device__ bf16 g_x0_hi[(size_t)NSTEP * B_ * E_];   // embedded inputs, all 127 steps
__device__ bf16 g_x0_lo[(size_t)NSTEP * B_ * E_];
__device__ float g_gi0[(size_t)NSTEP * B_ * G_];    // layer-0 input preacts (+bih)
__device__ float g_hf[2][2][B_ * H_];               // fp32 h [layer][parity]
__device__ bf16 g_h_hi[2][2][B_ * H_];
__device__ bf16 g_h_lo[2][2][B_ * H_];
__device__ bf16 g_xl_hi[B_ * H_];
__device__ bf16 g_xl_lo[B_ * H_];
__device__ bf16 g_top_hi[(size_t)(T_ - 1) * B_ * H_];
__device__ bf16 g_top_lo[(size_t)(T_ - 1) * B_ * H_];

__device__ __forceinline__ float sigm(float x) { return 1.0f / (1.0f + expf(-x)); }

__device__ __forceinline__ void split2(float x, bf16& hi, bf16& lo) {
    hi = __float2bfloat16(x);
    lo = __float2bfloat16(x - __bfloat162float(hi));
}

__device__ __forceinline__ void mma_acc(float (&d)[4],
    unsigned a0, unsigned a1, unsigned a2, unsigned a3, unsigned b0, unsigned b1)
{
    asm volatile(
        "mma.sync.aligned.m16n8k16.row.col.f32.bf16.bf16.f32 "
        "{%0,%1,%2,%3},{%4,%5,%6,%7},{%8,%9},{%0,%1,%2,%3};\n"
        : "+f"(d[0]), "+f"(d[1]), "+f"(d[2]), "+f"(d[3])
        : "r"(a0), "r"(a1), "r"(a2), "r"(a3), "r"(b0), "r"(b1));
}

// ---------------- init ----------------
__global__ void init_kernel(float* __restrict__ out) {
    const int idx = blockIdx.x * blockDim.x + threadIdx.x;
    const int stride = gridDim.x * blockDim.x;
    const bf16 z = __float2bfloat16(0.0f);
    for (int i = idx; i < B_ * H_; i += stride) {
        g_hf[0][0][i] = 0.0f; g_hf[1][0][i] = 0.0f;
        g_h_hi[0][0][i] = z; g_h_lo[0][0][i] = z;
        g_h_hi[1][0][i] = z; g_h_lo[1][0][i] = z;
    }
    for (int i = idx; i < B_ * V_; i += stride) {
        const int b = i / V_;
        const int v = i - b * V_;
        out[(size_t)b * (T_ * V_) + v] = 0.0f;
    }
}

// ---------------- one-shot weight split (all 9 regions) ----------------
__global__ void __launch_bounds__(256) split_all(
    const float* s0, const float* s1, const float* s2, const float* s3,
    const float* s4, const float* s5, const float* s6, const float* s7,
    const float* s8)
{
    const float* src; bf16* hi; bf16* lo; size_t n = GH_;
    switch (blockIdx.y) {
        case 0: src = s0; hi = g_wr_hi;            lo = g_wr_lo;            break;
        case 1: src = s1; hi = g_wr_hi + GH_;      lo = g_wr_lo + GH_;      break;
        case 2: src = s2; hi = g_wr_hi + 2 * GH_;  lo = g_wr_lo + 2 * GH_;  break;
        case 3: src = s3; hi = g_wr_hi + 3 * GH_;  lo = g_wr_lo + 3 * GH_;  break;
        case 4: src = s4; hi = g_wr_hi + 4 * GH_;  lo = g_wr_lo + 4 * GH_;  break;
        case 5: src = s5; hi = g_wr_hi + 5 * GH_;  lo = g_wr_lo + 5 * GH_;  break;
        case 6: src = s6; hi = g_wi0_hi;           lo = g_wi0_lo;           break;
        case 7: src = s7; hi = g_wi0_hi + GH_;     lo = g_wi0_lo + GH_;     break;
        default: src = s8; hi = g_wout_hi; lo = g_wout_lo; n = (size_t)V_ * H_; break;
    }
    size_t i = (size_t)blockIdx.x * blockDim.x + threadIdx.x;
    const size_t stride = (size_t)gridDim.x * blockDim.x;
    const size_t n4 = n >> 2;
    for (; i < n4; i += stride) {
        const float4 v = ((const float4*)src)[i];
        bf16 h0, l0, h1, l1, h2, l2, h3, l3;
        split2(v.x, h0, l0); split2(v.y, h1, l1);
        split2(v.z, h2, l2); split2(v.w, h3, l3);
        ((__nv_bfloat162*)hi)[2 * i]     = __halves2bfloat162(h0, h1);
        ((__nv_bfloat162*)hi)[2 * i + 1] = __halves2bfloat162(h2, h3);
        ((__nv_bfloat162*)lo)[2 * i]     = __halves2bfloat162(l0, l1);
        ((__nv_bfloat162*)lo)[2 * i + 1] = __halves2bfloat162(l2, l3);
    }
}

// ---------------- embedding gather + split, all 127 steps ----------------
__global__ void gather_all(const int* __restrict__ src_tokens, const int* __restrict__ trg,
                           const float* __restrict__ emb_enc, const float* __restrict__ emb_dec)
{
    const int total = NSTEP * B_ * (E_ / 4);
    int idx = blockIdx.x * blockDim.x + threadIdx.x;
    const int stride = gridDim.x * blockDim.x;
    for (; idx < total; idx += stride) {
        const int q = idx & 255;
        const int rb = idx >> 8;
        const int b = rb & 63;
        const int st = rb >> 6;
        int tok; const float* emb;
        if (st < S_) { tok = src_tokens[b * S_ + st]; emb = emb_enc; }
        else         { tok = trg[b * T_ + (st - S_)]; emb = emb_dec; }
        const float4 v = ((const float4*)(emb + (size_t)tok * E_))[q];
        bf16 h0, l0, h1, l1, h2, l2, h3, l3;
        split2(v.x, h0, l0); split2(v.y, h1, l1);
        split2(v.z, h2, l2); split2(v.w, h3, l3);
        const size_t base = (size_t)rb * E_ + q * 4;
        *(__nv_bfloat162*)(g_x0_hi + base)     = __halves2bfloat162(h0, h1);
        *(__nv_bfloat162*)(g_x0_hi + base + 2) = __halves2bfloat162(h2, h3);
        *(__nv_bfloat162*)(g_x0_lo + base)     = __halves2bfloat162(l0, l1);
        *(__nv_bfloat162*)(g_x0_lo + base + 2) = __halves2bfloat162(l2, l3);
    }
}

// ================= big batched MMA GEMM: 64 x 128 tile, 256 thr, prefetched ==
__device__ __forceinline__ void big_tile_mainloop(
    const bf16* __restrict__ Ahi, const bf16* __restrict__ Alo,
    const bf16* __restrict__ Bhi, const bf16* __restrict__ Blo,
    int n0, unsigned (*sA)[64 * AST2], unsigned (*sB)[128 * AST2],
    float (&acc)[8][4], int tid, int mt, int nh, int g, int c)
{
    int4 pa[2], pb[4];
    auto ld = [&](int k0) {
#pragma unroll
        for (int it = 0; it < 2; it++) {
            const int idx = tid + it * 256;
            const int pl = idx >> 8;
            const int r = (idx >> 2) & 63;
            const int q = idx & 3;
            pa[it] = *(const int4*)((pl ? Alo : Ahi) + (size_t)r * H_ + k0 + q * 8);
        }
#pragma unroll
        for (int it = 0; it < 4; it++) {
            const int idx = tid + it * 256;
            const int pl = idx >> 9;
            const int i = idx & 511;
            const int r = i >> 2;
            const int q = i & 3;
            pb[it] = *(const int4*)((pl ? Blo : Bhi) + (size_t)(n0 + r) * H_ + k0 + q * 8);
        }
    };
    auto st = [&]() {
#pragma unroll
        for (int it = 0; it < 2; it++) {
            const int idx = tid + it * 256;
            const int pl = idx >> 8;
            const int r = (idx >> 2) & 63;
            const int q = idx & 3;
            *(int4*)&sA[pl][r * AST2 + q * 4] = pa[it];
        }
#pragma unroll
        for (int it = 0; it < 4; it++) {
            const int idx = tid + it * 256;
            const int pl = idx >> 9;
            const int i = idx & 511;
            const int r = i >> 2;
            const int q = i & 3;
            *(int4*)&sB[pl][r * AST2 + q * 4] = pb[it];
        }
    };

    ld(0);
    for (int k0 = 0; k0 < H_; k0 += 32) {
        st();
        __syncthreads();
        if (k0 + 32 < H_) ld(k0 + 32);
#pragma unroll
        for (int ks = 0; ks < 2; ks++) {
            const int kw = ks * 8;
            const int ar = (mt * 16 + g) * AST2 + kw + c;
            const unsigned ah0 = sA[0][ar],     ah1 = sA[0][ar + 8 * AST2];
            const unsigned ah2 = sA[0][ar + 4], ah3 = sA[0][ar + 8 * AST2 + 4];
            const unsigned al0 = sA[1][ar],     al1 = sA[1][ar + 8 * AST2];
            const unsigned al2 = sA[1][ar + 4], al3 = sA[1][ar + 8 * AST2 + 4];
#pragma unroll
            for (int nt = 0; nt < 8; nt++) {
                const int br = (nh * 64 + nt * 8 + g) * AST2 + kw + c;
                const unsigned bh0 = sB[0][br], bh1 = sB[0][br + 4];
                const unsigned bl0 = sB[1][br], bl1 = sB[1][br + 4];
                mma_acc(acc[nt], ah0, ah1, ah2, ah3, bh0, bh1);
                mma_acc(acc[nt], ah0, ah1, ah2, ah3, bl0, bl1);
                mma_acc(acc[nt], al0, al1, al2, al3, bh0, bh1);
            }
        }
        __syncthreads();
    }
}

// ---- layer-0 input projection, all 127 steps: gi0 = X0 @ Wih0^T + bih -------
__global__ void __launch_bounds__(256) gi0_all(
    const float* __restrict__ bih_e, const float* __restrict__ bih_d)
{
    __shared__ unsigned sA[2][64 * AST2];
    __shared__ unsigned sB[2][128 * AST2];
    const int sidx = blockIdx.x;
    const int n0 = blockIdx.y * 128;
    const int tid = threadIdx.x, w = tid >> 5, lane = tid & 31;
    const int mt = w & 3, nh = w >> 2, g = lane >> 2, c = lane & 3;

    const size_t woff = (sidx < S_) ? 0 : GH_;
    const float* bias = (sidx < S_) ? bih_e : bih_d;

    float acc[8][4];
#pragma unroll
    for (int i = 0; i < 8; i++)
#pragma unroll
        for (int j = 0; j < 4; j++) acc[i][j] = 0.0f;

    big_tile_mainloop(g_x0_hi + (size_t)sidx * B_ * E_, g_x0_lo + (size_t)sidx * B_ * E_,
                      g_wi0_hi + woff, g_wi0_lo + woff, n0, sA, sB, acc, tid, mt, nh, g, c);

#pragma unroll
    for (int nt = 0; nt < 8; nt++) {
        const int v = n0 + nh * 64 + nt * 8 + 2 * c;
        const float b0 = bias[v], b1 = bias[v + 1];
#pragma unroll
        for (int hh = 0; hh < 2; hh++) {
            const int b = mt * 16 + g + hh * 8;
            float2 r;
            r.x = acc[nt][hh * 2 + 0] + b0;
            r.y = acc[nt][hh * 2 + 1] + b1;
            *(float2*)&g_gi0[((size_t)sidx * B_ + b) * G_ + v] = r;
        }
    }
}

// ---- vocab projection: out[b, s+1, v] = top[s,b,:] @ Wout^T + bout ----------
__global__ void __launch_bounds__(256) out_mma(const float* __restrict__ bout,
                                               float* __restrict__ out)
{
    __shared__ unsigned sA[2][64 * AST2];
    __shared__ unsigned sB[2][128 * AST2];
    const int s = blockIdx.x;
    const int n0 = blockIdx.y * 128;
    const int tid = threadIdx.x, w = tid >> 5, lane = tid & 31;
    const int mt = w & 3, nh = w >> 2, g = lane >> 2, c = lane & 3;

    float acc[8][4];
#pragma unroll
    for (int i = 0; i < 8; i++)
#pragma unroll
        for (int j = 0; j < 4; j++) acc[i][j] = 0.0f;

    big_tile_mainloop(g_top_hi + (size_t)s * B_ * H_, g_top_lo + (size_t)s * B_ * H_,
                      g_wout_hi, g_wout_lo, n0, sA, sB, acc, tid, mt, nh, g, c);

#pragma unroll
    for (int nt = 0; nt < 8; nt++) {
        const int v = n0 + nh * 64 + nt * 8 + 2 * c;
        const float b0 = __ldg(bout + v), b1 = __ldg(bout + v + 1);
#pragma unroll
        for (int hh = 0; hh < 2; hh++) {
            const int b = mt * 16 + g + hh * 8;
            float2 r;
            r.x = acc[nt][hh * 2 + 0] + b0;
            r.y = acc[nt][hh * 2 + 1] + b1;
            *(float2*)&out[(size_t)b * (T_ * V_) + (size_t)(s + 1) * V_ + v] = r;
        }
    }
}

// ================= recurrent GEMM pass (prefetched): 64 x 24 tile, 128 thr ===
__device__ __forceinline__ void gru_pass2(
    const bf16* __restrict__ Ahi, const bf16* __restrict__ Alo,
    const bf16* __restrict__ Whi, const bf16* __restrict__ Wlo,
    int j0, int kbase, int nchunks,
    unsigned* sA0, unsigned* sA1, unsigned* sW0, unsigned* sW1,
    float (&acc)[3][4], int tg, int m0, int g, int c)
{
    int4 pa[8], pw[3];
    auto ld = [&](int k0) {
#pragma unroll
        for (int it = 0; it < 8; it++) {
            const int idx = tg + it * 128;
            const int pl = idx >> 9;
            const int rem = idx & 511;
            const int r = rem >> 3, q = rem & 7;
            pa[it] = *(const int4*)((pl ? Alo : Ahi) + (size_t)r * H_ + k0 + q * 8);
        }
#pragma unroll
        for (int it = 0; it < 3; it++) {
            const int idx = tg + it * 128;
            const int pl = (idx >= 192) ? 1 : 0;
            const int i = idx - 192 * pl;
            const int r = i >> 3, q = i & 7;
            const int grow = (r >> 3) * H_ + j0 + (r & 7);
            pw[it] = *(const int4*)((pl ? Wlo : Whi) + (size_t)grow * H_ + k0 + q * 8);
        }
    };
    auto st = [&]() {
#pragma unroll
        for (int it = 0; it < 8; it++) {
            const int idx = tg + it * 128;
            const int pl = idx >> 9;
            const int rem = idx & 511;
            const int r = rem >> 3, q = rem & 7;
            *(int4*)&((pl ? sA1 : sA0)[r * ASTR + q * 4]) = pa[it];
        }
#pragma unroll
        for (int it = 0; it < 3; it++) {
            const int idx = tg + it * 128;
            const int pl = (idx >= 192) ? 1 : 0;
            const int i = idx - 192 * pl;
            const int r = i >> 3, q = i & 7;
            *(int4*)&((pl ? sW1 : sW0)[r * ASTR + q * 4]) = pw[it];
        }
    };

    ld(kbase);
    for (int ch = 0; ch < nchunks; ch++) {
        st();
        __syncthreads();
        if (ch + 1 < nchunks) ld(kbase + (ch + 1) * 64);
#pragma unroll
        for (int ks = 0; ks < 4; ks++) {
            const int kw = ks * 8;
            const int ar = (m0 + g) * ASTR + kw + c;
            const unsigned ah0 = sA0[ar],     ah1 = sA0[ar + 8 * ASTR];
            const unsigned ah2 = sA0[ar + 4], ah3 = sA0[ar + 8 * ASTR + 4];
            const unsigned al0 = sA1[ar],     al1 = sA1[ar + 8 * ASTR];
            const unsigned al2 = sA1[ar + 4], al3 = sA1[ar + 8 * ASTR + 4];
            unsigned bh0[3], bh1[3], bl0[3], bl1[3];
#pragma unroll
            for (int nt = 0; nt < 3; nt++) {
                const int wr = (nt * 8 + g) * ASTR + kw + c;
                bh0[nt] = sW0[wr]; bh1[nt] = sW0[wr + 4];
                bl0[nt] = sW1[wr]; bl1[nt] = sW1[wr + 4];
            }
#pragma unroll
            for (int nt = 0; nt < 3; nt++) mma_acc(acc[nt], ah0, ah1, ah2, ah3, bh0[nt], bh1[nt]);
#pragma unroll
            for (int nt = 0; nt < 3; nt++) mma_acc(acc[nt], ah0, ah1, ah2, ah3, bl0[nt], bl1[nt]);
#pragma unroll
            for (int nt = 0; nt < 3; nt++) mma_acc(acc[nt], al0, al1, al2, al3, bh0[nt], bh1[nt]);
        }
        __syncthreads();
    }
}

// C dump layout: C[b*25 + gate*8 + jj]
__device__ __forceinline__ void dump_frag(float* C, float (&acc)[3][4], int m0, int g, int c) {
#pragma unroll
    for (int nt = 0; nt < 3; nt++)
#pragma unroll
        for (int v = 0; v < 4; v++) {
            const int b = m0 + g + ((v >> 1) << 3);
            const int jj = 2 * c + (v & 1);
            C[b * 25 + nt * 8 + jj] = acc[nt][v];
        }
}

// ---- layer-0 step: gh = h0 @ Whh0^T, k-split over 2 groups; gi precomputed --
__global__ void __launch_bounds__(256) gru_l0(
    size_t woff, const float* __restrict__ bhh,
    const int* __restrict__ lengths, int t_state, int t_gi, int par)
{
    extern __shared__ unsigned smem_u[];
    const int tid = threadIdx.x;
    const int grp = tid >> 7;
    const int tg = tid & 127;
    const int w2 = tg >> 5, lane = tid & 31;
    const int g = lane >> 2, c = lane & 3, m0 = w2 * 16;
    const int j0 = blockIdx.x * 8;

    unsigned* sA0 = smem_u + (grp * 2 + 0) * SA_SZ;
    unsigned* sA1 = smem_u + (grp * 2 + 1) * SA_SZ;
    unsigned* sW0 = smem_u + 4 * SA_SZ + (grp * 2 + 0) * SW_SZ;
    unsigned* sW1 = smem_u + 4 * SA_SZ + (grp * 2 + 1) * SW_SZ;
    float* C = (float*)(smem_u + 4 * SA_SZ + 4 * SW_SZ);

    float acc[3][4];
#pragma unroll
    for (int i = 0; i < 3; i++)
#pragma unroll
        for (int j = 0; j < 4; j++) acc[i][j] = 0.0f;

    gru_pass2(g_h_hi[0][par], g_h_lo[0][par], g_wr_hi + woff, g_wr_lo + woff,
              j0, grp * 512, 8, sA0, sA1, sW0, sW1, acc, tg, m0, g, c);

    if (grp == 1) dump_frag(C, acc, m0, g, c);
    __syncthreads();

    if (grp == 0) {
        const float* hf = g_hf[0][par];
        float* hfn = g_hf[0][par ^ 1];
#pragma unroll
        for (int v = 0; v < 4; v++) {
            const int b = m0 + g + ((v >> 1) << 3);
            const int jj = 2 * c + (v & 1);
            const int j = j0 + jj;
            const float a_r = acc[0][v] + C[b * 25 + jj];
            const float a_z = acc[1][v] + C[b * 25 + 8 + jj];
            const float a_n = acc[2][v] + C[b * 25 + 16 + jj];
            const size_t gb = ((size_t)t_gi * B_ + b) * G_;
            const float r = sigm(g_gi0[gb + j] + a_r + bhh[j]);
            const float z = sigm(g_gi0[gb + H_ + j] + a_z + bhh[H_ + j]);
            const float n = tanhf(g_gi0[gb + 2 * H_ + j] + r * (a_n + bhh[2 * H_ + j]));
            const float hprev = hf[b * H_ + j];
            const float hnew = (1.0f - z) * n + z * hprev;
            bf16 xh, xl; split2(hnew, xh, xl);
            g_xl_hi[b * H_ + j] = xh; g_xl_lo[b * H_ + j] = xl;
            float hs = hnew;
            if (lengths && t_state >= lengths[b]) hs = hprev;
            hfn[b * H_ + j] = hs;
            bf16 sh, sl; split2(hs, sh, sl);
            g_h_hi[0][par ^ 1][b * H_ + j] = sh;
            g_h_lo[0][par ^ 1][b * H_ + j] = sl;
        }
    }
}

// ---- layer-1 step: group0 gi = xl @ Wih1^T, group1 gh = h1 @ Whh1^T ---------
__global__ void __launch_bounds__(256) gru_l1(
    size_t woffi, size_t woffh,
    const float* __restrict__ bih, const float* __restrict__ bhh,
    const int* __restrict__ lengths, int t_state, int par, int store_top, int step)
{
    extern __shared__ unsigned smem_u[];
    const int tid = threadIdx.x;
    const int grp = tid >> 7;
    const int tg = tid & 127;
    const int w2 = tg >> 5, lane = tid & 31;
    const int g = lane >> 2, c = lane & 3, m0 = w2 * 16;
    const int j0 = blockIdx.x * 8;

    unsigned* sA0 = smem_u + (grp * 2 + 0) * SA_SZ;
    unsigned* sA1 = smem_u + (grp * 2 + 1) * SA_SZ;
    unsigned* sW0 = smem_u + 4 * SA_SZ + (grp * 2 + 0) * SW_SZ;
    unsigned* sW1 = smem_u + 4 * SA_SZ + (grp * 2 + 1) * SW_SZ;
    float* C = (float*)(smem_u + 4 * SA_SZ + 4 * SW_SZ);

    const bf16 *Ahi, *Alo, *Whi, *Wlo;
    if (grp == 0) {
        Ahi = g_xl_hi; Alo = g_xl_lo;
        Whi = g_wr_hi + woffi; Wlo = g_wr_lo + woffi;
    } else {
        Ahi = g_h_hi[1][par]; Alo = g_h_lo[1][par];
        Whi = g_wr_hi + woffh; Wlo = g_wr_lo + woffh;
    }

    float acc[3][4];
#pragma unroll
    for (int i = 0; i < 3; i++)
#pragma unroll
        for (int j = 0; j < 4; j++) acc[i][j] = 0.0f;

    gru_pass2(Ahi, Alo, Whi, Wlo, j0, 0, 16, sA0, sA1, sW0, sW1, acc, tg, m0, g, c);

    if (grp == 1) dump_frag(C, acc, m0, g, c);   // gh partials
    __syncthreads();

    if (grp == 0) {
        const float* hf = g_hf[1][par];
        float* hfn = g_hf[1][par ^ 1];
#pragma unroll
        for (int v = 0; v < 4; v++) {
            const int b = m0 + g + ((v >> 1) << 3);
            const int jj = 2 * c + (v & 1);
            const int j = j0 + jj;
            const float ghr = C[b * 25 + jj];
            const float ghz = C[b * 25 + 8 + jj];
            const float ghn = C[b * 25 + 16 + jj];
            const float r = sigm(acc[0][v] + bih[j] + ghr + bhh[j]);
            const float z = sigm(acc[1][v] + bih[H_ + j] + ghz + bhh[H_ + j]);
            const float n = tanhf(acc[2][v] + bih[2 * H_ + j] + r * (ghn + bhh[2 * H_ + j]));
            const float hprev = hf[b * H_ + j];
            const float hnew = (1.0f - z) * n + z * hprev;
            if (store_top) {
                bf16 th, tl; split2(hnew, th, tl);
                g_top_hi[((size_t)step * B_ + b) * H_ + j] = th;
                g_top_lo[((size_t)step * B_ + b) * H_ + j] = tl;
            }
            float hs = hnew;
            if (lengths && t_state >= lengths[b]) hs = hprev;
            hfn[b * H_ + j] = hs;
            bf16 sh, sl; split2(hs, sh, sl);
            g_h_hi[1][par ^ 1][b * H_ + j] = sh;
            g_h_lo[1][par ^ 1][b * H_ + j] = sl;
        }
    }
}

// ------------------------------- host driver ---------------------------------
extern "C" void kernel_launch(void* const* d_in, const int* in_sizes, int n_in,
                              void* d_out, int out_size) {
    (void)in_sizes; (void)n_in; (void)out_size;
    const int*   src_tokens  = (const int*)d_in[0];
    const int*   src_lengths = (const int*)d_in[1];
    const int*   trg         = (const int*)d_in[2];
    const float* emb_enc = (const float*)d_in[3];
    const float* Wih_enc = (const float*)d_in[4];
    const float* Whh_enc = (const float*)d_in[5];
    const float* bih_enc = (const float*)d_in[6];
    const float* bhh_enc = (const float*)d_in[7];
    const float* emb_dec = (const float*)d_in[8];
    const float* Wih_dec = (const float*)d_in[9];
    const float* Whh_dec = (const float*)d_in[10];
    const float* bih_dec = (const float*)d_in[11];
    const float* bhh_dec = (const float*)d_in[12];
    const float* Wout    = (const float*)d_in[13];
    const float* bout    = (const float*)d_in[14];
    float* out = (float*)d_out;

    cudaFuncSetAttribute(gru_l0, cudaFuncAttributeMaxDynamicSharedMemorySize, GRU_SMEM_BYTES);
    cudaFuncSetAttribute(gru_l1, cudaFuncAttributeMaxDynamicSharedMemorySize, GRU_SMEM_BYTES);

    // launch 0
    init_kernel<<<512, 256>>>(out);
    // launch 1: all weight splits
    split_all<<<dim3(512, 9), 256>>>(Whh_enc, Whh_enc + GH_, Wih_enc + GH_,
                                     Whh_dec, Whh_dec + GH_, Wih_dec + GH_,
                                     Wih_enc, Wih_dec, Wout);
    // launch 2: all embedding gathers
    gather_all<<<2048, 256>>>(src_tokens, trg, emb_enc, emb_dec);
    // launch 3: layer-0 input projections for all 127 steps
    gi0_all<<<dim3(NSTEP, G_ / 128), 256>>>(bih_enc, bih_dec);

    // encoder recurrence (launches 4,5,...)
    for (int t = 0; t < S_; t++) {
        const int p = t & 1;
        gru_l0<<<H_ / 8, 256, GRU_SMEM_BYTES>>>(0 * GH_, bhh_enc, src_lengths, t, t, p);
        gru_l1<<<H_ / 8, 256, GRU_SMEM_BYTES>>>(2 * GH_, 1 * GH_, bih_enc + G_, bhh_enc + G_,
                                                src_lengths, t, p, 0, 0);
    }
    // decoder recurrence (encoder ran 64 steps -> parity continues at 0)
    for (int s = 0; s < T_ - 1; s++) {
        const int p = s & 1;
        gru_l0<<<H_ / 8, 256, GRU_SMEM_BYTES>>>(3 * GH_, bhh_dec, nullptr, s, S_ + s, p);
        gru_l1<<<H_ / 8, 256, GRU_SMEM_BYTES>>>(5 * GH_, 4 * GH_, bih_dec + G_, bhh_dec + G_,
                                                nullptr, s, p, 1, s);
    }

    // vocab projection (s fastest in grid.x -> Wout tile shared through L2)
    out_mma<<<dim3(T_ - 1, V_ / 128), 256>>>(bout, out);
}

// round 12
// speedup vs baseline: 3.1449x; 1.1196x over previous
#include <cuda_runtime.h>
#include <cuda_bf16.h>
#include <math.h>

#define B_ 64
#define S_ 64
#define T_ 64
#define H_ 1024
#define E_ 1024
#define G_ 3072
#define V_ 32000
#define NSTEP 127
#define ASTR 36                      // gru smem row stride (u32 words)
#define AST2 20                      // big-tile smem row stride (u32 words)
#define SA_SZ (64 * ASTR)
#define SW_SZ (24 * ASTR)
#define GRU_SMEM_WORDS (4 * SA_SZ + 4 * SW_SZ + 1600)
#define GRU_SMEM_BYTES (GRU_SMEM_WORDS * 4)
#define GH_ ((size_t)G_ * H_)

typedef __nv_bfloat16 bf16;

// ---------------- device-global scratch ----------------
__device__ bf16 g_wr_hi[6ull * G_ * H_];   // 0:Whh_e0 1:Whh_e1 2:Wih_e1 3:Whh_d0 4:Whh_d1 5:Wih_d1
__device__ bf16 g_wr_lo[6ull * G_ * H_];
__device__ bf16 g_wi0_hi[2ull * G_ * H_];  // layer-0 Wih: enc, dec
__device__ bf16 g_wi0_lo[2ull * G_ * H_];
__device__ bf16 g_wout_hi[(size_t)V_ * H_];
__device__ bf16 g_wout_lo[(size_t)V_ * H_];
__device__ bf16 g_x0_hi[(size_t)NSTEP * B_ * E_];
__device__ bf16 g_x0_lo[(size_t)NSTEP * B_ * E_];
__device__ float g_gi0[(size_t)NSTEP * B_ * G_];
__device__ float g_hf[2][2][B_ * H_];
__device__ bf16 g_h_hi[2][2][B_ * H_];
__device__ bf16 g_h_lo[2][2][B_ * H_];
__device__ bf16 g_xl_hi[B_ * H_];
__device__ bf16 g_xl_lo[B_ * H_];
__device__ bf16 g_top_hi[(size_t)(T_ - 1) * B_ * H_];
__device__ bf16 g_top_lo[(size_t)(T_ - 1) * B_ * H_];

__device__ __forceinline__ float sigm(float x) { return 1.0f / (1.0f + expf(-x)); }

__device__ __forceinline__ void split2(float x, bf16& hi, bf16& lo) {
    hi = __float2bfloat16(x);
    lo = __float2bfloat16(x - __bfloat162float(hi));
}

__device__ __forceinline__ void mma_acc(float (&d)[4],
    unsigned a0, unsigned a1, unsigned a2, unsigned a3, unsigned b0, unsigned b1)
{
    asm volatile(
        "mma.sync.aligned.m16n8k16.row.col.f32.bf16.bf16.f32 "
        "{%0,%1,%2,%3},{%4,%5,%6,%7},{%8,%9},{%0,%1,%2,%3};\n"
        : "+f"(d[0]), "+f"(d[1]), "+f"(d[2]), "+f"(d[3])
        : "r"(a0), "r"(a1), "r"(a2), "r"(a3), "r"(b0), "r"(b1));
}

__device__ __forceinline__ void ldsm_x4(unsigned& r0, unsigned& r1, unsigned& r2, unsigned& r3,
                                        unsigned addr)
{
    asm volatile("ldmatrix.sync.aligned.m8n8.x4.shared.b16 {%0,%1,%2,%3}, [%4];"
                 : "=r"(r0), "=r"(r1), "=r"(r2), "=r"(r3) : "r"(addr));
}
__device__ __forceinline__ void ldsm_x2(unsigned& r0, unsigned& r1, unsigned addr)
{
    asm volatile("ldmatrix.sync.aligned.m8n8.x2.shared.b16 {%0,%1}, [%2];"
                 : "=r"(r0), "=r"(r1) : "r"(addr));
}

// ---------------- init ----------------
__global__ void init_kernel(float* __restrict__ out) {
    const int idx = blockIdx.x * blockDim.x + threadIdx.x;
    const int stride = gridDim.x * blockDim.x;
    const bf16 z = __float2bfloat16(0.0f);
    for (int i = idx; i < B_ * H_; i += stride) {
        g_hf[0][0][i] = 0.0f; g_hf[1][0][i] = 0.0f;
        g_h_hi[0][0][i] = z; g_h_lo[0][0][i] = z;
        g_h_hi[1][0][i] = z; g_h_lo[1][0][i] = z;
    }
    for (int i = idx; i < B_ * V_; i += stride) {
        const int b = i / V_;
        const int v = i - b * V_;
        out[(size_t)b * (T_ * V_) + v] = 0.0f;
    }
}

// ---------------- one-shot weight split (all 9 regions) ----------------
__global__ void __launch_bounds__(256) split_all(
    const float* s0, const float* s1, const float* s2, const float* s3,
    const float* s4, const float* s5, const float* s6, const float* s7,
    const float* s8)
{
    const float* src; bf16* hi; bf16* lo; size_t n = GH_;
    switch (blockIdx.y) {
        case 0: src = s0; hi = g_wr_hi;            lo = g_wr_lo;            break;
        case 1: src = s1; hi = g_wr_hi + GH_;      lo = g_wr_lo + GH_;      break;
        case 2: src = s2; hi = g_wr_hi + 2 * GH_;  lo = g_wr_lo + 2 * GH_;  break;
        case 3: src = s3; hi = g_wr_hi + 3 * GH_;  lo = g_wr_lo + 3 * GH_;  break;
        case 4: src = s4; hi = g_wr_hi + 4 * GH_;  lo = g_wr_lo + 4 * GH_;  break;
        case 5: src = s5; hi = g_wr_hi + 5 * GH_;  lo = g_wr_lo + 5 * GH_;  break;
        case 6: src = s6; hi = g_wi0_hi;           lo = g_wi0_lo;           break;
        case 7: src = s7; hi = g_wi0_hi + GH_;     lo = g_wi0_lo + GH_;     break;
        default: src = s8; hi = g_wout_hi; lo = g_wout_lo; n = (size_t)V_ * H_; break;
    }
    size_t i = (size_t)blockIdx.x * blockDim.x + threadIdx.x;
    const size_t stride = (size_t)gridDim.x * blockDim.x;
    const size_t n4 = n >> 2;
    for (; i < n4; i += stride) {
        const float4 v = ((const float4*)src)[i];
        bf16 h0, l0, h1, l1, h2, l2, h3, l3;
        split2(v.x, h0, l0); split2(v.y, h1, l1);
        split2(v.z, h2, l2); split2(v.w, h3, l3);
        ((__nv_bfloat162*)hi)[2 * i]     = __halves2bfloat162(h0, h1);
        ((__nv_bfloat162*)hi)[2 * i + 1] = __halves2bfloat162(h2, h3);
        ((__nv_bfloat162*)lo)[2 * i]     = __halves2bfloat162(l0, l1);
        ((__nv_bfloat162*)lo)[2 * i + 1] = __halves2bfloat162(l2, l3);
    }
}

// ---------------- embedding gather + split, all 127 steps ----------------
__global__ void gather_all(const int* __restrict__ src_tokens, const int* __restrict__ trg,
                           const float* __restrict__ emb_enc, const float* __restrict__ emb_dec)
{
    const int total = NSTEP * B_ * (E_ / 4);
    int idx = blockIdx.x * blockDim.x + threadIdx.x;
    const int stride = gridDim.x * blockDim.x;
    for (; idx < total; idx += stride) {
        const int q = idx & 255;
        const int rb = idx >> 8;
        const int b = rb & 63;
        const int st = rb >> 6;
        int tok; const float* emb;
        if (st < S_) { tok = src_tokens[b * S_ + st]; emb = emb_enc; }
        else         { tok = trg[b * T_ + (st - S_)]; emb = emb_dec; }
        const float4 v = ((const float4*)(emb + (size_t)tok * E_))[q];
        bf16 h0, l0, h1, l1, h2, l2, h3, l3;
        split2(v.x, h0, l0); split2(v.y, h1, l1);
        split2(v.z, h2, l2); split2(v.w, h3, l3);
        const size_t base = (size_t)rb * E_ + q * 4;
        *(__nv_bfloat162*)(g_x0_hi + base)     = __halves2bfloat162(h0, h1);
        *(__nv_bfloat162*)(g_x0_hi + base + 2) = __halves2bfloat162(h2, h3);
        *(__nv_bfloat162*)(g_x0_lo + base)     = __halves2bfloat162(l0, l1);
        *(__nv_bfloat162*)(g_x0_lo + base + 2) = __halves2bfloat162(l2, l3);
    }
}

// ================= big batched MMA GEMM: 64 x 128 tile, 256 thr ==============
// smem layout: [row][k] bf16, row stride AST2 words. ldmatrix fragment loads.
__device__ __forceinline__ void big_tile_mainloop(
    const bf16* __restrict__ Ahi, const bf16* __restrict__ Alo,
    const bf16* __restrict__ Bhi, const bf16* __restrict__ Blo,
    int n0, unsigned (*sA)[64 * AST2], unsigned (*sB)[128 * AST2],
    float (&acc)[8][4], int tid, int mt, int nh)
{
    const int lane = tid & 31;
    const int mi = lane >> 3, ri = lane & 7;

    const unsigned sA0b = (unsigned)__cvta_generic_to_shared(sA[0]);
    const unsigned sA1b = (unsigned)__cvta_generic_to_shared(sA[1]);
    const unsigned sB0b = (unsigned)__cvta_generic_to_shared(sB[0]);
    const unsigned sB1b = (unsigned)__cvta_generic_to_shared(sB[1]);

    // A frag addr: matrices (m0..+7,kw),(m0+8..,kw),(m0..,kw+8),(m0+8..,kw+8)
    const unsigned aoff = ((mt * 16 + ri + (mi & 1) * 8) * AST2 + (mi >> 1) * 4) * 4;
    // B frag addr per np: matrices (n0,kw),(n0,kw+8),(n0+8,kw),(n0+8,kw+8)
    unsigned boff[4];
#pragma unroll
    for (int np = 0; np < 4; np++)
        boff[np] = ((nh * 64 + np * 16 + ri + (mi >> 1) * 8) * AST2 + (mi & 1) * 4) * 4;

    int4 pa[2], pb[4];
    auto ld = [&](int k0) {
#pragma unroll
        for (int it = 0; it < 2; it++) {
            const int idx = tid + it * 256;
            const int pl = idx >> 8;
            const int r = (idx >> 2) & 63;
            const int q = idx & 3;
            pa[it] = *(const int4*)((pl ? Alo : Ahi) + (size_t)r * H_ + k0 + q * 8);
        }
#pragma unroll
        for (int it = 0; it < 4; it++) {
            const int idx = tid + it * 256;
            const int pl = idx >> 9;
            const int i = idx & 511;
            const int r = i >> 2;
            const int q = i & 3;
            pb[it] = *(const int4*)((pl ? Blo : Bhi) + (size_t)(n0 + r) * H_ + k0 + q * 8);
        }
    };
    auto st = [&]() {
#pragma unroll
        for (int it = 0; it < 2; it++) {
            const int idx = tid + it * 256;
            const int pl = idx >> 8;
            const int r = (idx >> 2) & 63;
            const int q = idx & 3;
            *(int4*)&sA[pl][r * AST2 + q * 4] = pa[it];
        }
#pragma unroll
        for (int it = 0; it < 4; it++) {
            const int idx = tid + it * 256;
            const int pl = idx >> 9;
            const int i = idx & 511;
            const int r = i >> 2;
            const int q = i & 3;
            *(int4*)&sB[pl][r * AST2 + q * 4] = pb[it];
        }
    };

    ld(0);
    for (int k0 = 0; k0 < H_; k0 += 32) {
        st();
        __syncthreads();
        if (k0 + 32 < H_) ld(k0 + 32);
#pragma unroll
        for (int ks = 0; ks < 2; ks++) {
            const unsigned kb = ks * 32;              // 8 words
            unsigned ah0, ah1, ah2, ah3, al0, al1, al2, al3;
            ldsm_x4(ah0, ah1, ah2, ah3, sA0b + aoff + kb);
            ldsm_x4(al0, al1, al2, al3, sA1b + aoff + kb);
#pragma unroll
            for (int np = 0; np < 4; np++) {
                unsigned bh0, bh1, bh2, bh3, bl0, bl1, bl2, bl3;
                ldsm_x4(bh0, bh1, bh2, bh3, sB0b + boff[np] + kb);
                ldsm_x4(bl0, bl1, bl2, bl3, sB1b + boff[np] + kb);
                mma_acc(acc[np * 2],     ah0, ah1, ah2, ah3, bh0, bh1);
                mma_acc(acc[np * 2 + 1], ah0, ah1, ah2, ah3, bh2, bh3);
                mma_acc(acc[np * 2],     ah0, ah1, ah2, ah3, bl0, bl1);
                mma_acc(acc[np * 2 + 1], ah0, ah1, ah2, ah3, bl2, bl3);
                mma_acc(acc[np * 2],     al0, al1, al2, al3, bh0, bh1);
                mma_acc(acc[np * 2 + 1], al0, al1, al2, al3, bh2, bh3);
            }
        }
        __syncthreads();
    }
}

// ---- layer-0 input projection, all 127 steps ----
__global__ void __launch_bounds__(256) gi0_all(
    const float* __restrict__ bih_e, const float* __restrict__ bih_d)
{
    __shared__ unsigned sA[2][64 * AST2];
    __shared__ unsigned sB[2][128 * AST2];
    const int sidx = blockIdx.x;
    const int n0 = blockIdx.y * 128;
    const int tid = threadIdx.x, w = tid >> 5, lane = tid & 31;
    const int mt = w & 3, nh = w >> 2, g = lane >> 2, c = lane & 3;

    const size_t woff = (sidx < S_) ? 0 : GH_;
    const float* bias = (sidx < S_) ? bih_e : bih_d;

    float acc[8][4];
#pragma unroll
    for (int i = 0; i < 8; i++)
#pragma unroll
        for (int j = 0; j < 4; j++) acc[i][j] = 0.0f;

    big_tile_mainloop(g_x0_hi + (size_t)sidx * B_ * E_, g_x0_lo + (size_t)sidx * B_ * E_,
                      g_wi0_hi + woff, g_wi0_lo + woff, n0, sA, sB, acc, tid, mt, nh);

#pragma unroll
    for (int nt = 0; nt < 8; nt++) {
        const int v = n0 + nh * 64 + nt * 8 + 2 * c;
        const float b0 = bias[v], b1 = bias[v + 1];
#pragma unroll
        for (int hh = 0; hh < 2; hh++) {
            const int b = mt * 16 + g + hh * 8;
            float2 r;
            r.x = acc[nt][hh * 2 + 0] + b0;
            r.y = acc[nt][hh * 2 + 1] + b1;
            *(float2*)&g_gi0[((size_t)sidx * B_ + b) * G_ + v] = r;
        }
    }
}

// ---- vocab projection ----
__global__ void __launch_bounds__(256) out_mma(const float* __restrict__ bout,
                                               float* __restrict__ out)
{
    __shared__ unsigned sA[2][64 * AST2];
    __shared__ unsigned sB[2][128 * AST2];
    const int s = blockIdx.x;
    const int n0 = blockIdx.y * 128;
    const int tid = threadIdx.x, w = tid >> 5, lane = tid & 31;
    const int mt = w & 3, nh = w >> 2, g = lane >> 2, c = lane & 3;

    float acc[8][4];
#pragma unroll
    for (int i = 0; i < 8; i++)
#pragma unroll
        for (int j = 0; j < 4; j++) acc[i][j] = 0.0f;

    big_tile_mainloop(g_top_hi + (size_t)s * B_ * H_, g_top_lo + (size_t)s * B_ * H_,
                      g_wout_hi, g_wout_lo, n0, sA, sB, acc, tid, mt, nh);

#pragma unroll
    for (int nt = 0; nt < 8; nt++) {
        const int v = n0 + nh * 64 + nt * 8 + 2 * c;
        const float b0 = __ldg(bout + v), b1 = __ldg(bout + v + 1);
#pragma unroll
        for (int hh = 0; hh < 2; hh++) {
            const int b = mt * 16 + g + hh * 8;
            float2 r;
            r.x = acc[nt][hh * 2 + 0] + b0;
            r.y = acc[nt][hh * 2 + 1] + b1;
            *(float2*)&out[(size_t)b * (T_ * V_) + (size_t)(s + 1) * V_ + v] = r;
        }
    }
}

// ================= recurrent GEMM pass: 64 x 24 tile, 128 thr ================
__device__ __forceinline__ void gru_pass2(
    const bf16* __restrict__ Ahi, const bf16* __restrict__ Alo,
    const bf16* __restrict__ Whi, const bf16* __restrict__ Wlo,
    int j0, int kbase, int nchunks,
    unsigned* sA0, unsigned* sA1, unsigned* sW0, unsigned* sW1,
    float (&acc)[3][4], int tg, int m0)
{
    const int lane = tg & 31;
    const int mi = lane >> 3, ri = lane & 7;

    const unsigned sA0b = (unsigned)__cvta_generic_to_shared(sA0);
    const unsigned sA1b = (unsigned)__cvta_generic_to_shared(sA1);
    const unsigned sW0b = (unsigned)__cvta_generic_to_shared(sW0);
    const unsigned sW1b = (unsigned)__cvta_generic_to_shared(sW1);

    const unsigned aoff  = ((m0 + ri + (mi & 1) * 8) * ASTR + (mi >> 1) * 4) * 4;
    const unsigned w4off = ((ri + (mi >> 1) * 8) * ASTR + (mi & 1) * 4) * 4;       // gates 0,1
    const unsigned w2off = ((16 + ri) * ASTR + ((lane >> 3) & 1) * 4) * 4;          // gate 2

    int4 pa[8], pw[3];
    auto ld = [&](int k0) {
#pragma unroll
        for (int it = 0; it < 8; it++) {
            const int idx = tg + it * 128;
            const int pl = idx >> 9;
            const int rem = idx & 511;
            const int r = rem >> 3, q = rem & 7;
            pa[it] = *(const int4*)((pl ? Alo : Ahi) + (size_t)r * H_ + k0 + q * 8);
        }
#pragma unroll
        for (int it = 0; it < 3; it++) {
            const int idx = tg + it * 128;
            const int pl = (idx >= 192) ? 1 : 0;
            const int i = idx - 192 * pl;
            const int r = i >> 3, q = i & 7;
            const int grow = (r >> 3) * H_ + j0 + (r & 7);
            pw[it] = *(const int4*)((pl ? Wlo : Whi) + (size_t)grow * H_ + k0 + q * 8);
        }
    };
    auto st = [&]() {
#pragma unroll
        for (int it = 0; it < 8; it++) {
            const int idx = tg + it * 128;
            const int pl = idx >> 9;
            const int rem = idx & 511;
            const int r = rem >> 3, q = rem & 7;
            *(int4*)&((pl ? sA1 : sA0)[r * ASTR + q * 4]) = pa[it];
        }
#pragma unroll
        for (int it = 0; it < 3; it++) {
            const int idx = tg + it * 128;
            const int pl = (idx >= 192) ? 1 : 0;
            const int i = idx - 192 * pl;
            const int r = i >> 3, q = i & 7;
            *(int4*)&((pl ? sW1 : sW0)[r * ASTR + q * 4]) = pw[it];
        }
    };

    ld(kbase);
    for (int ch = 0; ch < nchunks; ch++) {
        st();
        __syncthreads();
        if (ch + 1 < nchunks) ld(kbase + (ch + 1) * 64);
#pragma unroll
        for (int ks = 0; ks < 4; ks++) {
            const unsigned kb = ks * 32;   // 8 words = 16 bf16
            unsigned ah0, ah1, ah2, ah3, al0, al1, al2, al3;
            ldsm_x4(ah0, ah1, ah2, ah3, sA0b + aoff + kb);
            ldsm_x4(al0, al1, al2, al3, sA1b + aoff + kb);
            unsigned bh0, bh1, bh2, bh3, bl0, bl1, bl2, bl3;
            unsigned ch0, ch1, cl0, cl1;
            ldsm_x4(bh0, bh1, bh2, bh3, sW0b + w4off + kb);
            ldsm_x4(bl0, bl1, bl2, bl3, sW1b + w4off + kb);
            ldsm_x2(ch0, ch1, sW0b + w2off + kb);
            ldsm_x2(cl0, cl1, sW1b + w2off + kb);
            mma_acc(acc[0], ah0, ah1, ah2, ah3, bh0, bh1);
            mma_acc(acc[1], ah0, ah1, ah2, ah3, bh2, bh3);
            mma_acc(acc[2], ah0, ah1, ah2, ah3, ch0, ch1);
            mma_acc(acc[0], ah0, ah1, ah2, ah3, bl0, bl1);
            mma_acc(acc[1], ah0, ah1, ah2, ah3, bl2, bl3);
            mma_acc(acc[2], ah0, ah1, ah2, ah3, cl0, cl1);
            mma_acc(acc[0], al0, al1, al2, al3, bh0, bh1);
            mma_acc(acc[1], al0, al1, al2, al3, bh2, bh3);
            mma_acc(acc[2], al0, al1, al2, al3, ch0, ch1);
        }
        __syncthreads();
    }
}

// C dump layout: C[b*25 + gate*8 + jj]
__device__ __forceinline__ void dump_frag(float* C, float (&acc)[3][4], int m0, int g, int c) {
#pragma unroll
    for (int nt = 0; nt < 3; nt++)
#pragma unroll
        for (int v = 0; v < 4; v++) {
            const int b = m0 + g + ((v >> 1) << 3);
            const int jj = 2 * c + (v & 1);
            C[b * 25 + nt * 8 + jj] = acc[nt][v];
        }
}

// ---- layer-0 step: gh = h0 @ Whh0^T, k-split over 2 groups ----
__global__ void __launch_bounds__(256) gru_l0(
    size_t woff, const float* __restrict__ bhh,
    const int* __restrict__ lengths, int t_state, int t_gi, int par)
{
    extern __shared__ unsigned smem_u[];
    const int tid = threadIdx.x;
    const int grp = tid >> 7;
    const int tg = tid & 127;
    const int w2 = tg >> 5, lane = tid & 31;
    const int g = lane >> 2, c = lane & 3, m0 = w2 * 16;
    const int j0 = blockIdx.x * 8;

    unsigned* sA0 = smem_u + (grp * 2 + 0) * SA_SZ;
    unsigned* sA1 = smem_u + (grp * 2 + 1) * SA_SZ;
    unsigned* sW0 = smem_u + 4 * SA_SZ + (grp * 2 + 0) * SW_SZ;
    unsigned* sW1 = smem_u + 4 * SA_SZ + (grp * 2 + 1) * SW_SZ;
    float* C = (float*)(smem_u + 4 * SA_SZ + 4 * SW_SZ);

    float acc[3][4];
#pragma unroll
    for (int i = 0; i < 3; i++)
#pragma unroll
        for (int j = 0; j < 4; j++) acc[i][j] = 0.0f;

    gru_pass2(g_h_hi[0][par], g_h_lo[0][par], g_wr_hi + woff, g_wr_lo + woff,
              j0, grp * 512, 8, sA0, sA1, sW0, sW1, acc, tg, m0);

    if (grp == 1) dump_frag(C, acc, m0, g, c);
    __syncthreads();

    if (grp == 0) {
        const float* hf = g_hf[0][par];
        float* hfn = g_hf[0][par ^ 1];
#pragma unroll
        for (int v = 0; v < 4; v++) {
            const int b = m0 + g + ((v >> 1) << 3);
            const int jj = 2 * c + (v & 1);
            const int j = j0 + jj;
            const float a_r = acc[0][v] + C[b * 25 + jj];
            const float a_z = acc[1][v] + C[b * 25 + 8 + jj];
            const float a_n = acc[2][v] + C[b * 25 + 16 + jj];
            const size_t gb = ((size_t)t_gi * B_ + b) * G_;
            const float r = sigm(g_gi0[gb + j] + a_r + bhh[j]);
            const float z = sigm(g_gi0[gb + H_ + j] + a_z + bhh[H_ + j]);
            const float n = tanhf(g_gi0[gb + 2 * H_ + j] + r * (a_n + bhh[2 * H_ + j]));
            const float hprev = hf[b * H_ + j];
            const float hnew = (1.0f - z) * n + z * hprev;
            bf16 xh, xl; split2(hnew, xh, xl);
            g_xl_hi[b * H_ + j] = xh; g_xl_lo[b * H_ + j] = xl;
            float hs = hnew;
            if (lengths && t_state >= lengths[b]) hs = hprev;
            hfn[b * H_ + j] = hs;
            bf16 sh, sl; split2(hs, sh, sl);
            g_h_hi[0][par ^ 1][b * H_ + j] = sh;
            g_h_lo[0][par ^ 1][b * H_ + j] = sl;
        }
    }
}

// ---- layer-1 step: group0 gi = xl @ Wih1^T, group1 gh = h1 @ Whh1^T ----
__global__ void __launch_bounds__(256) gru_l1(
    size_t woffi, size_t woffh,
    const float* __restrict__ bih, const float* __restrict__ bhh,
    const int* __restrict__ lengths, int t_state, int par, int store_top, int step)
{
    extern __shared__ unsigned smem_u[];
    const int tid = threadIdx.x;
    const int grp = tid >> 7;
    const int tg = tid & 127;
    const int w2 = tg >> 5, lane = tid & 31;
    const int g = lane >> 2, c = lane & 3, m0 = w2 * 16;
    const int j0 = blockIdx.x * 8;

    unsigned* sA0 = smem_u + (grp * 2 + 0) * SA_SZ;
    unsigned* sA1 = smem_u + (grp * 2 + 1) * SA_SZ;
    unsigned* sW0 = smem_u + 4 * SA_SZ + (grp * 2 + 0) * SW_SZ;
    unsigned* sW1 = smem_u + 4 * SA_SZ + (grp * 2 + 1) * SW_SZ;
    float* C = (float*)(smem_u + 4 * SA_SZ + 4 * SW_SZ);

    const bf16 *Ahi, *Alo, *Whi, *Wlo;
    if (grp == 0) {
        Ahi = g_xl_hi; Alo = g_xl_lo;
        Whi = g_wr_hi + woffi; Wlo = g_wr_lo + woffi;
    } else {
        Ahi = g_h_hi[1][par]; Alo = g_h_lo[1][par];
        Whi = g_wr_hi + woffh; Wlo = g_wr_lo + woffh;
    }

    float acc[3][4];
#pragma unroll
    for (int i = 0; i < 3; i++)
#pragma unroll
        for (int j = 0; j < 4; j++) acc[i][j] = 0.0f;

    gru_pass2(Ahi, Alo, Whi, Wlo, j0, 0, 16, sA0, sA1, sW0, sW1, acc, tg, m0);

    if (grp == 1) dump_frag(C, acc, m0, g, c);   // gh partials
    __syncthreads();

    if (grp == 0) {
        const float* hf = g_hf[1][par];
        float* hfn = g_hf[1][par ^ 1];
#pragma unroll
        for (int v = 0; v < 4; v++) {
            const int b = m0 + g + ((v >> 1) << 3);
            const int jj = 2 * c + (v & 1);
            const int j = j0 + jj;
            const float ghr = C[b * 25 + jj];
            const float ghz = C[b * 25 + 8 + jj];
            const float ghn = C[b * 25 + 16 + jj];
            const float r = sigm(acc[0][v] + bih[j] + ghr + bhh[j]);
            const float z = sigm(acc[1][v] + bih[H_ + j] + ghz + bhh[H_ + j]);
            const float n = tanhf(acc[2][v] + bih[2 * H_ + j] + r * (ghn + bhh[2 * H_ + j]));
            const float hprev = hf[b * H_ + j];
            const float hnew = (1.0f - z) * n + z * hprev;
            if (store_top) {
                bf16 th, tl; split2(hnew, th, tl);
                g_top_hi[((size_t)step * B_ + b) * H_ + j] = th;
                g_top_lo[((size_t)step * B_ + b) * H_ + j] = tl;
            }
            float hs = hnew;
            if (lengths && t_state >= lengths[b]) hs = hprev;
            hfn[b * H_ + j] = hs;
            bf16 sh, sl; split2(hs, sh, sl);
            g_h_hi[1][par ^ 1][b * H_ + j] = sh;
            g_h_lo[1][par ^ 1][b * H_ + j] = sl;
        }
    }
}

// ------------------------------- host driver ---------------------------------
extern "C" void kernel_launch(void* const* d_in, const int* in_sizes, int n_in,
                              void* d_out, int out_size) {
    (void)in_sizes; (void)n_in; (void)out_size;
    const int*   src_tokens  = (const int*)d_in[0];
    const int*   src_lengths = (const int*)d_in[1];
    const int*   trg         = (const int*)d_in[2];
    const float* emb_enc = (const float*)d_in[3];
    const float* Wih_enc = (const float*)d_in[4];
    const float* Whh_enc = (const float*)d_in[5];
    const float* bih_enc = (const float*)d_in[6];
    const float* bhh_enc = (const float*)d_in[7];
    const float* emb_dec = (const float*)d_in[8];
    const float* Wih_dec = (const float*)d_in[9];
    const float* Whh_dec = (const float*)d_in[10];
    const float* bih_dec = (const float*)d_in[11];
    const float* bhh_dec = (const float*)d_in[12];
    const float* Wout    = (const float*)d_in[13];
    const float* bout    = (const float*)d_in[14];
    float* out = (float*)d_out;

    cudaFuncSetAttribute(gru_l0, cudaFuncAttributeMaxDynamicSharedMemorySize, GRU_SMEM_BYTES);
    cudaFuncSetAttribute(gru_l1, cudaFuncAttributeMaxDynamicSharedMemorySize, GRU_SMEM_BYTES);

    init_kernel<<<512, 256>>>(out);
    split_all<<<dim3(512, 9), 256>>>(Whh_enc, Whh_enc + GH_, Wih_enc + GH_,
                                     Whh_dec, Whh_dec + GH_, Wih_dec + GH_,
                                     Wih_enc, Wih_dec, Wout);
    gather_all<<<2048, 256>>>(src_tokens, trg, emb_enc, emb_dec);
    gi0_all<<<dim3(NSTEP, G_ / 128), 256>>>(bih_enc, bih_dec);

    for (int t = 0; t < S_; t++) {
        const int p = t & 1;
        gru_l0<<<H_ / 8, 256, GRU_SMEM_BYTES>>>(0 * GH_, bhh_enc, src_lengths, t, t, p);
        gru_l1<<<H_ / 8, 256, GRU_SMEM_BYTES>>>(2 * GH_, 1 * GH_, bih_enc + G_, bhh_enc + G_,
                                                src_lengths, t, p, 0, 0);
    }
    for (int s = 0; s < T_ - 1; s++) {
        const int p = s & 1;
        gru_l0<<<H_ / 8, 256, GRU_SMEM_BYTES>>>(3 * GH_, bhh_dec, nullptr, s, S_ + s, p);
        gru_l1<<<H_ / 8, 256, GRU_SMEM_BYTES>>>(5 * GH_, 4 * GH_, bih_dec + G_, bhh_dec + G_,
                                                nullptr, s, p, 1, s);
    }

    out_mma<<<dim3(T_ - 1, V_ / 128), 256>>>(bout, out);
}

// round 14
// speedup vs baseline: 3.3858x; 1.0766x over previous
#include <cuda_runtime.h>
#include <cuda_bf16.h>
#include <math.h>

#define B_ 64
#define S_ 64
#define T_ 64
#define H_ 1024
#define E_ 1024
#define G_ 3072
#define V_ 32000
#define NSTEP 127
#define NSTEP_PAD 128
#define ASTR 36                      // gru smem row stride (u32 words)
#define AST2 20                      // big-tile smem row stride (u32 words)
#define SA_SZ (64 * ASTR)
#define SW_SZ (24 * ASTR)
#define GRP_WORDS (2 * SA_SZ + 2 * SW_SZ)           // per-group smem block
#define GRU_SMEM_WORDS (4 * GRP_WORDS + 3 * 1600)   // 4 groups + 3 C buffers
#define GRU_SMEM_BYTES (GRU_SMEM_WORDS * 4)
#define GH_ ((size_t)G_ * H_)

typedef __nv_bfloat16 bf16;

// ---------------- device-global scratch ----------------
__device__ bf16 g_wr_hi[6ull * G_ * H_];   // 0:Whh_e0 1:Whh_e1 2:Wih_e1 3:Whh_d0 4:Whh_d1 5:Wih_d1
__device__ bf16 g_wr_lo[6ull * G_ * H_];
__device__ bf16 g_wi0_hi[2ull * G_ * H_];  // layer-0 Wih: enc, dec
__device__ bf16 g_wi0_lo[2ull * G_ * H_];
__device__ bf16 g_wout_hi[(size_t)V_ * H_];
__device__ bf16 g_wout_lo[(size_t)V_ * H_];
__device__ bf16 g_x0_hi[(size_t)NSTEP_PAD * B_ * E_];   // padded to 128 steps (zeros)
__device__ bf16 g_x0_lo[(size_t)NSTEP_PAD * B_ * E_];
__device__ float g_gi0[(size_t)NSTEP_PAD * B_ * G_];
__device__ float g_hf[2][2][B_ * H_];
__device__ bf16 g_h_hi[2][2][B_ * H_];
__device__ bf16 g_h_lo[2][2][B_ * H_];
__device__ bf16 g_xl_hi[B_ * H_];
__device__ bf16 g_xl_lo[B_ * H_];
__device__ bf16 g_top_hi[(size_t)T_ * B_ * H_];         // padded to 64 steps
__device__ bf16 g_top_lo[(size_t)T_ * B_ * H_];

__device__ __forceinline__ float sigm(float x) { return 1.0f / (1.0f + expf(-x)); }

__device__ __forceinline__ void split2(float x, bf16& hi, bf16& lo) {
    hi = __float2bfloat16(x);
    lo = __float2bfloat16(x - __bfloat162float(hi));
}

__device__ __forceinline__ void mma_acc(float (&d)[4],
    unsigned a0, unsigned a1, unsigned a2, unsigned a3, unsigned b0, unsigned b1)
{
    asm volatile(
        "mma.sync.aligned.m16n8k16.row.col.f32.bf16.bf16.f32 "
        "{%0,%1,%2,%3},{%4,%5,%6,%7},{%8,%9},{%0,%1,%2,%3};\n"
        : "+f"(d[0]), "+f"(d[1]), "+f"(d[2]), "+f"(d[3])
        : "r"(a0), "r"(a1), "r"(a2), "r"(a3), "r"(b0), "r"(b1));
}

__device__ __forceinline__ void ldsm_x4(unsigned& r0, unsigned& r1, unsigned& r2, unsigned& r3,
                                        unsigned addr)
{
    asm volatile("ldmatrix.sync.aligned.m8n8.x4.shared.b16 {%0,%1,%2,%3}, [%4];"
                 : "=r"(r0), "=r"(r1), "=r"(r2), "=r"(r3) : "r"(addr));
}
__device__ __forceinline__ void ldsm_x2(unsigned& r0, unsigned& r1, unsigned addr)
{
    asm volatile("ldmatrix.sync.aligned.m8n8.x2.shared.b16 {%0,%1}, [%2];"
                 : "=r"(r0), "=r"(r1) : "r"(addr));
}

// ---------------- init ----------------
__global__ void init_kernel(float* __restrict__ out) {
    const int idx = blockIdx.x * blockDim.x + threadIdx.x;
    const int stride = gridDim.x * blockDim.x;
    const bf16 z = __float2bfloat16(0.0f);
    for (int i = idx; i < B_ * H_; i += stride) {
        g_hf[0][0][i] = 0.0f; g_hf[1][0][i] = 0.0f;
        g_h_hi[0][0][i] = z; g_h_lo[0][0][i] = z;
        g_h_hi[1][0][i] = z; g_h_lo[1][0][i] = z;
    }
    for (int i = idx; i < B_ * V_; i += stride) {
        const int b = i / V_;
        const int v = i - b * V_;
        out[(size_t)b * (T_ * V_) + v] = 0.0f;
    }
}

// ---------------- one-shot weight split (all 9 regions) ----------------
__global__ void __launch_bounds__(256) split_all(
    const float* s0, const float* s1, const float* s2, const float* s3,
    const float* s4, const float* s5, const float* s6, const float* s7,
    const float* s8)
{
    const float* src; bf16* hi; bf16* lo; size_t n = GH_;
    switch (blockIdx.y) {
        case 0: src = s0; hi = g_wr_hi;            lo = g_wr_lo;            break;
        case 1: src = s1; hi = g_wr_hi + GH_;      lo = g_wr_lo + GH_;      break;
        case 2: src = s2; hi = g_wr_hi + 2 * GH_;  lo = g_wr_lo + 2 * GH_;  break;
        case 3: src = s3; hi = g_wr_hi + 3 * GH_;  lo = g_wr_lo + 3 * GH_;  break;
        case 4: src = s4; hi = g_wr_hi + 4 * GH_;  lo = g_wr_lo + 4 * GH_;  break;
        case 5: src = s5; hi = g_wr_hi + 5 * GH_;  lo = g_wr_lo + 5 * GH_;  break;
        case 6: src = s6; hi = g_wi0_hi;           lo = g_wi0_lo;           break;
        case 7: src = s7; hi = g_wi0_hi + GH_;     lo = g_wi0_lo + GH_;     break;
        default: src = s8; hi = g_wout_hi; lo = g_wout_lo; n = (size_t)V_ * H_; break;
    }
    size_t i = (size_t)blockIdx.x * blockDim.x + threadIdx.x;
    const size_t stride = (size_t)gridDim.x * blockDim.x;
    const size_t n4 = n >> 2;
    for (; i < n4; i += stride) {
        const float4 v = ((const float4*)src)[i];
        bf16 h0, l0, h1, l1, h2, l2, h3, l3;
        split2(v.x, h0, l0); split2(v.y, h1, l1);
        split2(v.z, h2, l2); split2(v.w, h3, l3);
        ((__nv_bfloat162*)hi)[2 * i]     = __halves2bfloat162(h0, h1);
        ((__nv_bfloat162*)hi)[2 * i + 1] = __halves2bfloat162(h2, h3);
        ((__nv_bfloat162*)lo)[2 * i]     = __halves2bfloat162(l0, l1);
        ((__nv_bfloat162*)lo)[2 * i + 1] = __halves2bfloat162(l2, l3);
    }
}

// ---------------- embedding gather + split, all 127 steps ----------------
__global__ void gather_all(const int* __restrict__ src_tokens, const int* __restrict__ trg,
                           const float* __restrict__ emb_enc, const float* __restrict__ emb_dec)
{
    const int total = NSTEP * B_ * (E_ / 4);
    int idx = blockIdx.x * blockDim.x + threadIdx.x;
    const int stride = gridDim.x * blockDim.x;
    for (; idx < total; idx += stride) {
        const int q = idx & 255;
        const int rb = idx >> 8;
        const int b = rb & 63;
        const int st = rb >> 6;
        int tok; const float* emb;
        if (st < S_) { tok = src_tokens[b * S_ + st]; emb = emb_enc; }
        else         { tok = trg[b * T_ + (st - S_)]; emb = emb_dec; }
        const float4 v = ((const float4*)(emb + (size_t)tok * E_))[q];
        bf16 h0, l0, h1, l1, h2, l2, h3, l3;
        split2(v.x, h0, l0); split2(v.y, h1, l1);
        split2(v.z, h2, l2); split2(v.w, h3, l3);
        const size_t base = (size_t)rb * E_ + q * 4;
        *(__nv_bfloat162*)(g_x0_hi + base)     = __halves2bfloat162(h0, h1);
        *(__nv_bfloat162*)(g_x0_hi + base + 2) = __halves2bfloat162(h2, h3);
        *(__nv_bfloat162*)(g_x0_lo + base)     = __halves2bfloat162(l0, l1);
        *(__nv_bfloat162*)(g_x0_lo + base + 2) = __halves2bfloat162(l2, l3);
    }
}

// ================= big batched MMA GEMM: 128 x 128 tile, 256 thr =============
// 8 warps: wm = w&3 (M strip of 32), wn = w>>2 (N strip of 64).
__device__ __forceinline__ void big_tile_mainloop(
    const bf16* __restrict__ Ahi, const bf16* __restrict__ Alo,
    const bf16* __restrict__ Bhi, const bf16* __restrict__ Blo,
    int n0, unsigned (*sA)[128 * AST2], unsigned (*sB)[128 * AST2],
    float (&acc)[2][8][4], int tid, int wm, int wn)
{
    const int lane = tid & 31;
    const int mi = lane >> 3, ri = lane & 7;

    const unsigned sA0b = (unsigned)__cvta_generic_to_shared(sA[0]);
    const unsigned sA1b = (unsigned)__cvta_generic_to_shared(sA[1]);
    const unsigned sB0b = (unsigned)__cvta_generic_to_shared(sB[0]);
    const unsigned sB1b = (unsigned)__cvta_generic_to_shared(sB[1]);

    unsigned aoff[2];
#pragma unroll
    for (int ma = 0; ma < 2; ma++)
        aoff[ma] = ((wm * 32 + ma * 16 + ri + (mi & 1) * 8) * AST2 + (mi >> 1) * 4) * 4;
    unsigned boff[4];
#pragma unroll
    for (int np = 0; np < 4; np++)
        boff[np] = ((wn * 64 + np * 16 + ri + (mi >> 1) * 8) * AST2 + (mi & 1) * 4) * 4;

    int4 pa[4], pb[4];
    auto ld = [&](int k0) {
#pragma unroll
        for (int it = 0; it < 4; it++) {
            const int idx = tid + it * 256;
            const int pl = idx >> 9;
            const int rem = idx & 511;
            const int r = rem >> 2;
            const int q = rem & 3;
            pa[it] = *(const int4*)((pl ? Alo : Ahi) + (size_t)r * H_ + k0 + q * 8);
            pb[it] = *(const int4*)((pl ? Blo : Bhi) + (size_t)(n0 + r) * H_ + k0 + q * 8);
        }
    };
    auto st = [&]() {
#pragma unroll
        for (int it = 0; it < 4; it++) {
            const int idx = tid + it * 256;
            const int pl = idx >> 9;
            const int rem = idx & 511;
            const int r = rem >> 2;
            const int q = rem & 3;
            *(int4*)&sA[pl][r * AST2 + q * 4] = pa[it];
            *(int4*)&sB[pl][r * AST2 + q * 4] = pb[it];
        }
    };

    ld(0);
    for (int k0 = 0; k0 < H_; k0 += 32) {
        st();
        __syncthreads();
        if (k0 + 32 < H_) ld(k0 + 32);
#pragma unroll
        for (int ks = 0; ks < 2; ks++) {
            const unsigned kb = ks * 32;
            unsigned ah[2][4], al[2][4];
#pragma unroll
            for (int ma = 0; ma < 2; ma++) {
                ldsm_x4(ah[ma][0], ah[ma][1], ah[ma][2], ah[ma][3], sA0b + aoff[ma] + kb);
                ldsm_x4(al[ma][0], al[ma][1], al[ma][2], al[ma][3], sA1b + aoff[ma] + kb);
            }
#pragma unroll
            for (int np = 0; np < 4; np++) {
                unsigned bh0, bh1, bh2, bh3, bl0, bl1, bl2, bl3;
                ldsm_x4(bh0, bh1, bh2, bh3, sB0b + boff[np] + kb);
                ldsm_x4(bl0, bl1, bl2, bl3, sB1b + boff[np] + kb);
#pragma unroll
                for (int ma = 0; ma < 2; ma++) {
                    mma_acc(acc[ma][np * 2],     ah[ma][0], ah[ma][1], ah[ma][2], ah[ma][3], bh0, bh1);
                    mma_acc(acc[ma][np * 2 + 1], ah[ma][0], ah[ma][1], ah[ma][2], ah[ma][3], bh2, bh3);
                    mma_acc(acc[ma][np * 2],     ah[ma][0], ah[ma][1], ah[ma][2], ah[ma][3], bl0, bl1);
                    mma_acc(acc[ma][np * 2 + 1], ah[ma][0], ah[ma][1], ah[ma][2], ah[ma][3], bl2, bl3);
                    mma_acc(acc[ma][np * 2],     al[ma][0], al[ma][1], al[ma][2], al[ma][3], bh0, bh1);
                    mma_acc(acc[ma][np * 2 + 1], al[ma][0], al[ma][1], al[ma][2], al[ma][3], bh2, bh3);
                }
            }
        }
        __syncthreads();
    }
}

// ---- layer-0 input projection, all steps (2 steps per M-tile) ----
__global__ void __launch_bounds__(256) gi0_all(
    const float* __restrict__ bih_e, const float* __restrict__ bih_d)
{
    __shared__ unsigned sA[2][128 * AST2];
    __shared__ unsigned sB[2][128 * AST2];
    const int bx = blockIdx.x;                  // 64 M-tiles (tiles 0-31 enc, 32-63 dec)
    const int n0 = blockIdx.y * 128;
    const int tid = threadIdx.x, w = tid >> 5, lane = tid & 31;
    const int wm = w & 3, wn = w >> 2, g = lane >> 2, c = lane & 3;

    const size_t woff = (bx < 32) ? 0 : GH_;
    const float* bias = (bx < 32) ? bih_e : bih_d;

    float acc[2][8][4];
#pragma unroll
    for (int ma = 0; ma < 2; ma++)
#pragma unroll
        for (int i = 0; i < 8; i++)
#pragma unroll
            for (int j = 0; j < 4; j++) acc[ma][i][j] = 0.0f;

    big_tile_mainloop(g_x0_hi + (size_t)bx * 128 * E_, g_x0_lo + (size_t)bx * 128 * E_,
                      g_wi0_hi + woff, g_wi0_lo + woff, n0, sA, sB, acc, tid, wm, wn);

#pragma unroll
    for (int nt = 0; nt < 8; nt++) {
        const int v = n0 + wn * 64 + nt * 8 + 2 * c;
        const float b0 = bias[v], b1 = bias[v + 1];
#pragma unroll
        for (int ma = 0; ma < 2; ma++)
#pragma unroll
            for (int hh = 0; hh < 2; hh++) {
                const size_t rg = (size_t)bx * 128 + wm * 32 + ma * 16 + g + hh * 8;
                float2 r;
                r.x = acc[ma][nt][hh * 2 + 0] + b0;
                r.y = acc[ma][nt][hh * 2 + 1] + b1;
                *(float2*)&g_gi0[rg * G_ + v] = r;
            }
    }
}

// ---- vocab projection (2 steps per M-tile) ----
__global__ void __launch_bounds__(256) out_mma(const float* __restrict__ bout,
                                               float* __restrict__ out)
{
    __shared__ unsigned sA[2][128 * AST2];
    __shared__ unsigned sB[2][128 * AST2];
    const int bx = blockIdx.x;                  // 32 M-tiles
    const int n0 = blockIdx.y * 128;
    const int tid = threadIdx.x, w = tid >> 5, lane = tid & 31;
    const int wm = w & 3, wn = w >> 2, g = lane >> 2, c = lane & 3;

    float acc[2][8][4];
#pragma unroll
    for (int ma = 0; ma < 2; ma++)
#pragma unroll
        for (int i = 0; i < 8; i++)
#pragma unroll
            for (int j = 0; j < 4; j++) acc[ma][i][j] = 0.0f;

    big_tile_mainloop(g_top_hi + (size_t)bx * 128 * H_, g_top_lo + (size_t)bx * 128 * H_,
                      g_wout_hi, g_wout_lo, n0, sA, sB, acc, tid, wm, wn);

#pragma unroll
    for (int nt = 0; nt < 8; nt++) {
        const int v = n0 + wn * 64 + nt * 8 + 2 * c;
        const float b0 = __ldg(bout + v), b1 = __ldg(bout + v + 1);
#pragma unroll
        for (int ma = 0; ma < 2; ma++)
#pragma unroll
            for (int hh = 0; hh < 2; hh++) {
                const int rg = bx * 128 + wm * 32 + ma * 16 + g + hh * 8;
                const int s = rg >> 6, b = rg & 63;
                if (s < T_ - 1) {
                    float2 r;
                    r.x = acc[ma][nt][hh * 2 + 0] + b0;
                    r.y = acc[ma][nt][hh * 2 + 1] + b1;
                    *(float2*)&out[(size_t)b * (T_ * V_) + (size_t)(s + 1) * V_ + v] = r;
                }
            }
    }
}

// ================= recurrent GEMM pass: 64 x 24 tile per group, 128 thr ======
__device__ __forceinline__ void gru_pass2(
    const bf16* __restrict__ Ahi, const bf16* __restrict__ Alo,
    const bf16* __restrict__ Whi, const bf16* __restrict__ Wlo,
    int j0, int kbase, int nchunks,
    unsigned* sA0, unsigned* sA1, unsigned* sW0, unsigned* sW1,
    float (&acc)[3][4], int tg, int m0)
{
    const int lane = tg & 31;
    const int mi = lane >> 3, ri = lane & 7;

    const unsigned sA0b = (unsigned)__cvta_generic_to_shared(sA0);
    const unsigned sA1b = (unsigned)__cvta_generic_to_shared(sA1);
    const unsigned sW0b = (unsigned)__cvta_generic_to_shared(sW0);
    const unsigned sW1b = (unsigned)__cvta_generic_to_shared(sW1);

    const unsigned aoff  = ((m0 + ri + (mi & 1) * 8) * ASTR + (mi >> 1) * 4) * 4;
    const unsigned w4off = ((ri + (mi >> 1) * 8) * ASTR + (mi & 1) * 4) * 4;       // gates 0,1
    const unsigned w2off = ((16 + ri) * ASTR + ((lane >> 3) & 1) * 4) * 4;          // gate 2

    int4 pa[8], pw[3];
    auto ld = [&](int k0) {
#pragma unroll
        for (int it = 0; it < 8; it++) {
            const int idx = tg + it * 128;
            const int pl = idx >> 9;
            const int rem = idx & 511;
            const int r = rem >> 3, q = rem & 7;
            pa[it] = *(const int4*)((pl ? Alo : Ahi) + (size_t)r * H_ + k0 + q * 8);
        }
#pragma unroll
        for (int it = 0; it < 3; it++) {
            const int idx = tg + it * 128;
            const int pl = (idx >= 192) ? 1 : 0;
            const int i = idx - 192 * pl;
            const int r = i >> 3, q = i & 7;
            const int grow = (r >> 3) * H_ + j0 + (r & 7);
            pw[it] = *(const int4*)((pl ? Wlo : Whi) + (size_t)grow * H_ + k0 + q * 8);
        }
    };
    auto st = [&]() {
#pragma unroll
        for (int it = 0; it < 8; it++) {
            const int idx = tg + it * 128;
            const int pl = idx >> 9;
            const int rem = idx & 511;
            const int r = rem >> 3, q = rem & 7;
            *(int4*)&((pl ? sA1 : sA0)[r * ASTR + q * 4]) = pa[it];
        }
#pragma unroll
        for (int it = 0; it < 3; it++) {
            const int idx = tg + it * 128;
            const int pl = (idx >= 192) ? 1 : 0;
            const int i = idx - 192 * pl;
            const int r = i >> 3, q = i & 7;
            *(int4*)&((pl ? sW1 : sW0)[r * ASTR + q * 4]) = pw[it];
        }
    };

    ld(kbase);
    for (int ch = 0; ch < nchunks; ch++) {
        st();
        __syncthreads();
        if (ch + 1 < nchunks) ld(kbase + (ch + 1) * 64);
#pragma unroll
        for (int ks = 0; ks < 4; ks++) {
            const unsigned kb = ks * 32;
            unsigned ah0, ah1, ah2, ah3, al0, al1, al2, al3;
            ldsm_x4(ah0, ah1, ah2, ah3, sA0b + aoff + kb);
            ldsm_x4(al0, al1, al2, al3, sA1b + aoff + kb);
            unsigned bh0, bh1, bh2, bh3, bl0, bl1, bl2, bl3;
            unsigned ch0, ch1, cl0, cl1;
            ldsm_x4(bh0, bh1, bh2, bh3, sW0b + w4off + kb);
            ldsm_x4(bl0, bl1, bl2, bl3, sW1b + w4off + kb);
            ldsm_x2(ch0, ch1, sW0b + w2off + kb);
            ldsm_x2(cl0, cl1, sW1b + w2off + kb);
            mma_acc(acc[0], ah0, ah1, ah2, ah3, bh0, bh1);
            mma_acc(acc[1], ah0, ah1, ah2, ah3, bh2, bh3);
            mma_acc(acc[2], ah0, ah1, ah2, ah3, ch0, ch1);
            mma_acc(acc[0], ah0, ah1, ah2, ah3, bl0, bl1);
            mma_acc(acc[1], ah0, ah1, ah2, ah3, bl2, bl3);
            mma_acc(acc[2], ah0, ah1, ah2, ah3, cl0, cl1);
            mma_acc(acc[0], al0, al1, al2, al3, bh0, bh1);
            mma_acc(acc[1], al0, al1, al2, al3, bh2, bh3);
            mma_acc(acc[2], al0, al1, al2, al3, ch0, ch1);
        }
        __syncthreads();
    }
}

// C dump layout: C[b*25 + gate*8 + jj]
__device__ __forceinline__ void dump_frag(float* C, float (&acc)[3][4], int m0, int g, int c) {
#pragma unroll
    for (int nt = 0; nt < 3; nt++)
#pragma unroll
        for (int v = 0; v < 4; v++) {
            const int b = m0 + g + ((v >> 1) << 3);
            const int jj = 2 * c + (v & 1);
            C[b * 25 + nt * 8 + jj] = acc[nt][v];
        }
}

// ---- layer-0 step: gh = h0 @ Whh0^T, k-split over 4 groups ----
__global__ void __launch_bounds__(512) gru_l0(
    size_t woff, const float* __restrict__ bhh,
    const int* __restrict__ lengths, int t_state, int t_gi, int par)
{
    extern __shared__ unsigned smem_u[];
    const int tid = threadIdx.x;
    const int grp = tid >> 7;              // 0..3
    const int tg = tid & 127;
    const int w2 = tg >> 5, lane = tid & 31;
    const int g = lane >> 2, c = lane & 3, m0 = w2 * 16;
    const int j0 = blockIdx.x * 8;

    unsigned* gbase = smem_u + grp * GRP_WORDS;
    unsigned* sA0 = gbase;
    unsigned* sA1 = gbase + SA_SZ;
    unsigned* sW0 = gbase + 2 * SA_SZ;
    unsigned* sW1 = gbase + 2 * SA_SZ + SW_SZ;
    float* C = (float*)(smem_u + 4 * GRP_WORDS);

    float acc[3][4];
#pragma unroll
    for (int i = 0; i < 3; i++)
#pragma unroll
        for (int j = 0; j < 4; j++) acc[i][j] = 0.0f;

    gru_pass2(g_h_hi[0][par], g_h_lo[0][par], g_wr_hi + woff, g_wr_lo + woff,
              j0, grp * 256, 4, sA0, sA1, sW0, sW1, acc, tg, m0);

    if (grp > 0) dump_frag(C + (grp - 1) * 1600, acc, m0, g, c);
    __syncthreads();

    if (grp == 0) {
        const float* hf = g_hf[0][par];
        float* hfn = g_hf[0][par ^ 1];
#pragma unroll
        for (int v = 0; v < 4; v++) {
            const int b = m0 + g + ((v >> 1) << 3);
            const int jj = 2 * c + (v & 1);
            const int j = j0 + jj;
            const float a_r = acc[0][v] + C[b * 25 + jj]          + C[1600 + b * 25 + jj]          + C[3200 + b * 25 + jj];
            const float a_z = acc[1][v] + C[b * 25 + 8 + jj]      + C[1600 + b * 25 + 8 + jj]      + C[3200 + b * 25 + 8 + jj];
            const float a_n = acc[2][v] + C[b * 25 + 16 + jj]     + C[1600 + b * 25 + 16 + jj]     + C[3200 + b * 25 + 16 + jj];
            const size_t gb = ((size_t)t_gi * B_ + b) * G_;
            const float r = sigm(g_gi0[gb + j] + a_r + bhh[j]);
            const float z = sigm(g_gi0[gb + H_ + j] + a_z + bhh[H_ + j]);
            const float n = tanhf(g_gi0[gb + 2 * H_ + j] + r * (a_n + bhh[2 * H_ + j]));
            const float hprev = hf[b * H_ + j];
            const float hnew = (1.0f - z) * n + z * hprev;
            bf16 xh, xl; split2(hnew, xh, xl);
            g_xl_hi[b * H_ + j] = xh; g_xl_lo[b * H_ + j] = xl;
            float hs = hnew;
            if (lengths && t_state >= lengths[b]) hs = hprev;
            hfn[b * H_ + j] = hs;
            bf16 sh, sl; split2(hs, sh, sl);
            g_h_hi[0][par ^ 1][b * H_ + j] = sh;
            g_h_lo[0][par ^ 1][b * H_ + j] = sl;
        }
    }
}

// ---- layer-1 step: (2 GEMMs) x (2 k-halves) over 4 groups ----
// grp: 0 = (gi,k0), 1 = (gi,k1), 2 = (gh,k0), 3 = (gh,k1)
__global__ void __launch_bounds__(512) gru_l1(
    size_t woffi, size_t woffh,
    const float* __restrict__ bih, const float* __restrict__ bhh,
    const int* __restrict__ lengths, int t_state, int par, int store_top, int step)
{
    extern __shared__ unsigned smem_u[];
    const int tid = threadIdx.x;
    const int grp = tid >> 7;
    const int tg = tid & 127;
    const int w2 = tg >> 5, lane = tid & 31;
    const int g = lane >> 2, c = lane & 3, m0 = w2 * 16;
    const int j0 = blockIdx.x * 8;

    unsigned* gbase = smem_u + grp * GRP_WORDS;
    unsigned* sA0 = gbase;
    unsigned* sA1 = gbase + SA_SZ;
    unsigned* sW0 = gbase + 2 * SA_SZ;
    unsigned* sW1 = gbase + 2 * SA_SZ + SW_SZ;
    float* C = (float*)(smem_u + 4 * GRP_WORDS);

    const bf16 *Ahi, *Alo, *Whi, *Wlo;
    if (grp < 2) {
        Ahi = g_xl_hi; Alo = g_xl_lo;
        Whi = g_wr_hi + woffi; Wlo = g_wr_lo + woffi;
    } else {
        Ahi = g_h_hi[1][par]; Alo = g_h_lo[1][par];
        Whi = g_wr_hi + woffh; Wlo = g_wr_lo + woffh;
    }
    const int kbase = (grp & 1) * 512;

    float acc[3][4];
#pragma unroll
    for (int i = 0; i < 3; i++)
#pragma unroll
        for (int j = 0; j < 4; j++) acc[i][j] = 0.0f;

    gru_pass2(Ahi, Alo, Whi, Wlo, j0, kbase, 8, sA0, sA1, sW0, sW1, acc, tg, m0);

    if (grp > 0) dump_frag(C + (grp - 1) * 1600, acc, m0, g, c);
    __syncthreads();

    if (grp == 0) {
        const float* hf = g_hf[1][par];
        float* hfn = g_hf[1][par ^ 1];
#pragma unroll
        for (int v = 0; v < 4; v++) {
            const int b = m0 + g + ((v >> 1) << 3);
            const int jj = 2 * c + (v & 1);
            const int j = j0 + jj;
            const float gir = acc[0][v] + C[b * 25 + jj];
            const float giz = acc[1][v] + C[b * 25 + 8 + jj];
            const float gin = acc[2][v] + C[b * 25 + 16 + jj];
            const float ghr = C[1600 + b * 25 + jj]      + C[3200 + b * 25 + jj];
            const float ghz = C[1600 + b * 25 + 8 + jj]  + C[3200 + b * 25 + 8 + jj];
            const float ghn = C[1600 + b * 25 + 16 + jj] + C[3200 + b * 25 + 16 + jj];
            const float r = sigm(gir + bih[j] + ghr + bhh[j]);
            const float z = sigm(giz + bih[H_ + j] + ghz + bhh[H_ + j]);
            const float n = tanhf(gin + bih[2 * H_ + j] + r * (ghn + bhh[2 * H_ + j]));
            const float hprev = hf[b * H_ + j];
            const float hnew = (1.0f - z) * n + z * hprev;
            if (store_top) {
                bf16 th, tl; split2(hnew, th, tl);
                g_top_hi[((size_t)step * B_ + b) * H_ + j] = th;
                g_top_lo[((size_t)step * B_ + b) * H_ + j] = tl;
            }
            float hs = hnew;
            if (lengths && t_state >= lengths[b]) hs = hprev;
            hfn[b * H_ + j] = hs;
            bf16 sh, sl; split2(hs, sh, sl);
            g_h_hi[1][par ^ 1][b * H_ + j] = sh;
            g_h_lo[1][par ^ 1][b * H_ + j] = sl;
        }
    }
}

// ------------------------------- host driver ---------------------------------
extern "C" void kernel_launch(void* const* d_in, const int* in_sizes, int n_in,
                              void* d_out, int out_size) {
    (void)in_sizes; (void)n_in; (void)out_size;
    const int*   src_tokens  = (const int*)d_in[0];
    const int*   src_lengths = (const int*)d_in[1];
    const int*   trg         = (const int*)d_in[2];
    const float* emb_enc = (const float*)d_in[3];
    const float* Wih_enc = (const float*)d_in[4];
    const float* Whh_enc = (const float*)d_in[5];
    const float* bih_enc = (const float*)d_in[6];
    const float* bhh_enc = (const float*)d_in[7];
    const float* emb_dec = (const float*)d_in[8];
    const float* Wih_dec = (const float*)d_in[9];
    const float* Whh_dec = (const float*)d_in[10];
    const float* bih_dec = (const float*)d_in[11];
    const float* bhh_dec = (const float*)d_in[12];
    const float* Wout    = (const float*)d_in[13];
    const float* bout    = (const float*)d_in[14];
    float* out = (float*)d_out;

    cudaFuncSetAttribute(gru_l0, cudaFuncAttributeMaxDynamicSharedMemorySize, GRU_SMEM_BYTES);
    cudaFuncSetAttribute(gru_l1, cudaFuncAttributeMaxDynamicSharedMemorySize, GRU_SMEM_BYTES);

    init_kernel<<<512, 256>>>(out);
    split_all<<<dim3(512, 9), 256>>>(Whh_enc, Whh_enc + GH_, Wih_enc + GH_,
                                     Whh_dec, Whh_dec + GH_, Wih_dec + GH_,
                                     Wih_enc, Wih_dec, Wout);
    gather_all<<<2048, 256>>>(src_tokens, trg, emb_enc, emb_dec);
    gi0_all<<<dim3(64, G_ / 128), 256>>>(bih_enc, bih_dec);

    for (int t = 0; t < S_; t++) {
        const int p = t & 1;
        gru_l0<<<H_ / 8, 512, GRU_SMEM_BYTES>>>(0 * GH_, bhh_enc, src_lengths, t, t, p);
        gru_l1<<<H_ / 8, 512, GRU_SMEM_BYTES>>>(2 * GH_, 1 * GH_, bih_enc + G_, bhh_enc + G_,
                                                src_lengths, t, p, 0, 0);
    }
    for (int s = 0; s < T_ - 1; s++) {
        const int p = s & 1;
        gru_l0<<<H_ / 8, 512, GRU_SMEM_BYTES>>>(3 * GH_, bhh_dec, nullptr, s, S_ + s, p);
        gru_l1<<<H_ / 8, 512, GRU_SMEM_BYTES>>>(5 * GH_, 4 * GH_, bih_dec + G_, bhh_dec + G_,
                                                nullptr, s, p, 1, s);
    }

    out_mma<<<dim3(32, V_ / 128), 256>>>(bout, out);
}

// round 15
// speedup vs baseline: 3.4446x; 1.0174x over previous
#include <cuda_runtime.h>
#include <cuda_bf16.h>
#include <math.h>

#define B_ 64
#define S_ 64
#define T_ 64
#define H_ 1024
#define E_ 1024
#define G_ 3072
#define V_ 32000
#define NSTEP 127
#define NSTEP_PAD 128
#define ASTR 36                      // gru smem row stride (u32 words)
#define AST2 20                      // big-tile smem row stride (u32 words)
#define SA_SZ (64 * ASTR)
#define SW_SZ (24 * ASTR)
#define GRP_WORDS (2 * SA_SZ + 2 * SW_SZ)           // per-group smem block
#define GRU_SMEM_WORDS (4 * GRP_WORDS + 3 * 1600)   // 4 groups + 3 C buffers
#define GRU_SMEM_BYTES (GRU_SMEM_WORDS * 4)
#define GH_ ((size_t)G_ * H_)

typedef __nv_bfloat16 bf16;

// ---------------- device-global scratch ----------------
__device__ bf16 g_wr_hi[6ull * G_ * H_];   // 0:Whh_e0 1:Whh_e1 2:Wih_e1 3:Whh_d0 4:Whh_d1 5:Wih_d1
__device__ bf16 g_wr_lo[6ull * G_ * H_];
__device__ bf16 g_wi0_hi[2ull * G_ * H_];  // layer-0 Wih: enc, dec
__device__ bf16 g_wi0_lo[2ull * G_ * H_];
__device__ bf16 g_wout_hi[(size_t)V_ * H_];
__device__ bf16 g_wout_lo[(size_t)V_ * H_];
__device__ bf16 g_x0_hi[(size_t)NSTEP_PAD * B_ * E_];   // padded to 128 steps
__device__ bf16 g_x0_lo[(size_t)NSTEP_PAD * B_ * E_];
__device__ float g_gi0[(size_t)NSTEP_PAD * B_ * G_];
__device__ float g_hf[2][2][B_ * H_];
__device__ bf16 g_h_hi[2][2][B_ * H_];
__device__ bf16 g_h_lo[2][2][B_ * H_];
__device__ bf16 g_xl_hi[B_ * H_];
__device__ bf16 g_xl_lo[B_ * H_];
__device__ bf16 g_top_hi[(size_t)T_ * B_ * H_];
__device__ bf16 g_top_lo[(size_t)T_ * B_ * H_];
__device__ unsigned g_ctr;                 // grid-barrier counter (reset per launch)

__device__ __forceinline__ float sigm(float x) { return 1.0f / (1.0f + expf(-x)); }

__device__ __forceinline__ void split2(float x, bf16& hi, bf16& lo) {
    hi = __float2bfloat16(x);
    lo = __float2bfloat16(x - __bfloat162float(hi));
}

__device__ __forceinline__ void mma_acc(float (&d)[4],
    unsigned a0, unsigned a1, unsigned a2, unsigned a3, unsigned b0, unsigned b1)
{
    asm volatile(
        "mma.sync.aligned.m16n8k16.row.col.f32.bf16.bf16.f32 "
        "{%0,%1,%2,%3},{%4,%5,%6,%7},{%8,%9},{%0,%1,%2,%3};\n"
        : "+f"(d[0]), "+f"(d[1]), "+f"(d[2]), "+f"(d[3])
        : "r"(a0), "r"(a1), "r"(a2), "r"(a3), "r"(b0), "r"(b1));
}

__device__ __forceinline__ void ldsm_x4(unsigned& r0, unsigned& r1, unsigned& r2, unsigned& r3,
                                        unsigned addr)
{
    asm volatile("ldmatrix.sync.aligned.m8n8.x4.shared.b16 {%0,%1,%2,%3}, [%4];"
                 : "=r"(r0), "=r"(r1), "=r"(r2), "=r"(r3) : "r"(addr));
}
__device__ __forceinline__ void ldsm_x2(unsigned& r0, unsigned& r1, unsigned addr)
{
    asm volatile("ldmatrix.sync.aligned.m8n8.x2.shared.b16 {%0,%1}, [%2];"
                 : "=r"(r0), "=r"(r1) : "r"(addr));
}

// software grid barrier: all CTAs co-resident (1 CTA/SM, 128 <= 148 SMs)
__device__ __forceinline__ void grid_barrier(unsigned& bar_no, int nb) {
    __syncthreads();
    __threadfence();
    if (threadIdx.x == 0) {
        const unsigned target = (bar_no + 1u) * (unsigned)nb;
        atomicAdd(&g_ctr, 1u);
        while (*(volatile unsigned*)&g_ctr < target) __nanosleep(64);
    }
    bar_no++;
    __syncthreads();
}

// ---------------- init ----------------
__global__ void init_kernel(float* __restrict__ out) {
    const int idx = blockIdx.x * blockDim.x + threadIdx.x;
    const int stride = gridDim.x * blockDim.x;
    const bf16 z = __float2bfloat16(0.0f);
    if (idx == 0) g_ctr = 0u;
    for (int i = idx; i < B_ * H_; i += stride) {
        g_hf[0][0][i] = 0.0f; g_hf[1][0][i] = 0.0f;
        g_h_hi[0][0][i] = z; g_h_lo[0][0][i] = z;
        g_h_hi[1][0][i] = z; g_h_lo[1][0][i] = z;
    }
    for (int i = idx; i < B_ * V_; i += stride) {
        const int b = i / V_;
        const int v = i - b * V_;
        out[(size_t)b * (T_ * V_) + v] = 0.0f;
    }
}

// ---------------- one-shot weight split (all 9 regions) ----------------
__global__ void __launch_bounds__(256) split_all(
    const float* s0, const float* s1, const float* s2, const float* s3,
    const float* s4, const float* s5, const float* s6, const float* s7,
    const float* s8)
{
    const float* src; bf16* hi; bf16* lo; size_t n = GH_;
    switch (blockIdx.y) {
        case 0: src = s0; hi = g_wr_hi;            lo = g_wr_lo;            break;
        case 1: src = s1; hi = g_wr_hi + GH_;      lo = g_wr_lo + GH_;      break;
        case 2: src = s2; hi = g_wr_hi + 2 * GH_;  lo = g_wr_lo + 2 * GH_;  break;
        case 3: src = s3; hi = g_wr_hi + 3 * GH_;  lo = g_wr_lo + 3 * GH_;  break;
        case 4: src = s4; hi = g_wr_hi + 4 * GH_;  lo = g_wr_lo + 4 * GH_;  break;
        case 5: src = s5; hi = g_wr_hi + 5 * GH_;  lo = g_wr_lo + 5 * GH_;  break;
        case 6: src = s6; hi = g_wi0_hi;           lo = g_wi0_lo;           break;
        case 7: src = s7; hi = g_wi0_hi + GH_;     lo = g_wi0_lo + GH_;     break;
        default: src = s8; hi = g_wout_hi; lo = g_wout_lo; n = (size_t)V_ * H_; break;
    }
    size_t i = (size_t)blockIdx.x * blockDim.x + threadIdx.x;
    const size_t stride = (size_t)gridDim.x * blockDim.x;
    const size_t n4 = n >> 2;
    for (; i < n4; i += stride) {
        const float4 v = ((const float4*)src)[i];
        bf16 h0, l0, h1, l1, h2, l2, h3, l3;
        split2(v.x, h0, l0); split2(v.y, h1, l1);
        split2(v.z, h2, l2); split2(v.w, h3, l3);
        ((__nv_bfloat162*)hi)[2 * i]     = __halves2bfloat162(h0, h1);
        ((__nv_bfloat162*)hi)[2 * i + 1] = __halves2bfloat162(h2, h3);
        ((__nv_bfloat162*)lo)[2 * i]     = __halves2bfloat162(l0, l1);
        ((__nv_bfloat162*)lo)[2 * i + 1] = __halves2bfloat162(l2, l3);
    }
}

// ---------------- embedding gather + split, all 127 steps ----------------
__global__ void gather_all(const int* __restrict__ src_tokens, const int* __restrict__ trg,
                           const float* __restrict__ emb_enc, const float* __restrict__ emb_dec)
{
    const int total = NSTEP * B_ * (E_ / 4);
    int idx = blockIdx.x * blockDim.x + threadIdx.x;
    const int stride = gridDim.x * blockDim.x;
    for (; idx < total; idx += stride) {
        const int q = idx & 255;
        const int rb = idx >> 8;
        const int b = rb & 63;
        const int st = rb >> 6;
        int tok; const float* emb;
        if (st < S_) { tok = src_tokens[b * S_ + st]; emb = emb_enc; }
        else         { tok = trg[b * T_ + (st - S_)]; emb = emb_dec; }
        const float4 v = ((const float4*)(emb + (size_t)tok * E_))[q];
        bf16 h0, l0, h1, l1, h2, l2, h3, l3;
        split2(v.x, h0, l0); split2(v.y, h1, l1);
        split2(v.z, h2, l2); split2(v.w, h3, l3);
        const size_t base = (size_t)rb * E_ + q * 4;
        *(__nv_bfloat162*)(g_x0_hi + base)     = __halves2bfloat162(h0, h1);
        *(__nv_bfloat162*)(g_x0_hi + base + 2) = __halves2bfloat162(h2, h3);
        *(__nv_bfloat162*)(g_x0_lo + base)     = __halves2bfloat162(l0, l1);
        *(__nv_bfloat162*)(g_x0_lo + base + 2) = __halves2bfloat162(l2, l3);
    }
}

// ================= big batched MMA GEMM: 128 x 128 tile, 256 thr =============
__device__ __forceinline__ void big_tile_mainloop(
    const bf16* __restrict__ Ahi, const bf16* __restrict__ Alo,
    const bf16* __restrict__ Bhi, const bf16* __restrict__ Blo,
    int n0, unsigned (*sA)[128 * AST2], unsigned (*sB)[128 * AST2],
    float (&acc)[2][8][4], int tid, int wm, int wn)
{
    const int lane = tid & 31;
    const int mi = lane >> 3, ri = lane & 7;

    const unsigned sA0b = (unsigned)__cvta_generic_to_shared(sA[0]);
    const unsigned sA1b = (unsigned)__cvta_generic_to_shared(sA[1]);
    const unsigned sB0b = (unsigned)__cvta_generic_to_shared(sB[0]);
    const unsigned sB1b = (unsigned)__cvta_generic_to_shared(sB[1]);

    unsigned aoff[2];
#pragma unroll
    for (int ma = 0; ma < 2; ma++)
        aoff[ma] = ((wm * 32 + ma * 16 + ri + (mi & 1) * 8) * AST2 + (mi >> 1) * 4) * 4;
    unsigned boff[4];
#pragma unroll
    for (int np = 0; np < 4; np++)
        boff[np] = ((wn * 64 + np * 16 + ri + (mi >> 1) * 8) * AST2 + (mi & 1) * 4) * 4;

    int4 pa[4], pb[4];
    auto ld = [&](int k0) {
#pragma unroll
        for (int it = 0; it < 4; it++) {
            const int idx = tid + it * 256;
            const int pl = idx >> 9;
            const int rem = idx & 511;
            const int r = rem >> 2;
            const int q = rem & 3;
            pa[it] = *(const int4*)((pl ? Alo : Ahi) + (size_t)r * H_ + k0 + q * 8);
            pb[it] = *(const int4*)((pl ? Blo : Bhi) + (size_t)(n0 + r) * H_ + k0 + q * 8);
        }
    };
    auto st = [&]() {
#pragma unroll
        for (int it = 0; it < 4; it++) {
            const int idx = tid + it * 256;
            const int pl = idx >> 9;
            const int rem = idx & 511;
            const int r = rem >> 2;
            const int q = rem & 3;
            *(int4*)&sA[pl][r * AST2 + q * 4] = pa[it];
            *(int4*)&sB[pl][r * AST2 + q * 4] = pb[it];
        }
    };

    ld(0);
    for (int k0 = 0; k0 < H_; k0 += 32) {
        st();
        __syncthreads();
        if (k0 + 32 < H_) ld(k0 + 32);
#pragma unroll
        for (int ks = 0; ks < 2; ks++) {
            const unsigned kb = ks * 32;
            unsigned ah[2][4], al[2][4];
#pragma unroll
            for (int ma = 0; ma < 2; ma++) {
                ldsm_x4(ah[ma][0], ah[ma][1], ah[ma][2], ah[ma][3], sA0b + aoff[ma] + kb);
                ldsm_x4(al[ma][0], al[ma][1], al[ma][2], al[ma][3], sA1b + aoff[ma] + kb);
            }
#pragma unroll
            for (int np = 0; np < 4; np++) {
                unsigned bh0, bh1, bh2, bh3, bl0, bl1, bl2, bl3;
                ldsm_x4(bh0, bh1, bh2, bh3, sB0b + boff[np] + kb);
                ldsm_x4(bl0, bl1, bl2, bl3, sB1b + boff[np] + kb);
#pragma unroll
                for (int ma = 0; ma < 2; ma++) {
                    mma_acc(acc[ma][np * 2],     ah[ma][0], ah[ma][1], ah[ma][2], ah[ma][3], bh0, bh1);
                    mma_acc(acc[ma][np * 2 + 1], ah[ma][0], ah[ma][1], ah[ma][2], ah[ma][3], bh2, bh3);
                    mma_acc(acc[ma][np * 2],     ah[ma][0], ah[ma][1], ah[ma][2], ah[ma][3], bl0, bl1);
                    mma_acc(acc[ma][np * 2 + 1], ah[ma][0], ah[ma][1], ah[ma][2], ah[ma][3], bl2, bl3);
                    mma_acc(acc[ma][np * 2],     al[ma][0], al[ma][1], al[ma][2], al[ma][3], bh0, bh1);
                    mma_acc(acc[ma][np * 2 + 1], al[ma][0], al[ma][1], al[ma][2], al[ma][3], bh2, bh3);
                }
            }
        }
        __syncthreads();
    }
}

// ---- layer-0 input projection, all steps (2 steps per M-tile) ----
__global__ void __launch_bounds__(256) gi0_all(
    const float* __restrict__ bih_e, const float* __restrict__ bih_d)
{
    __shared__ unsigned sA[2][128 * AST2];
    __shared__ unsigned sB[2][128 * AST2];
    const int bx = blockIdx.x;
    const int n0 = blockIdx.y * 128;
    const int tid = threadIdx.x, w = tid >> 5, lane = tid & 31;
    const int wm = w & 3, wn = w >> 2, g = lane >> 2, c = lane & 3;

    const size_t woff = (bx < 32) ? 0 : GH_;
    const float* bias = (bx < 32) ? bih_e : bih_d;

    float acc[2][8][4];
#pragma unroll
    for (int ma = 0; ma < 2; ma++)
#pragma unroll
        for (int i = 0; i < 8; i++)
#pragma unroll
            for (int j = 0; j < 4; j++) acc[ma][i][j] = 0.0f;

    big_tile_mainloop(g_x0_hi + (size_t)bx * 128 * E_, g_x0_lo + (size_t)bx * 128 * E_,
                      g_wi0_hi + woff, g_wi0_lo + woff, n0, sA, sB, acc, tid, wm, wn);

#pragma unroll
    for (int nt = 0; nt < 8; nt++) {
        const int v = n0 + wn * 64 + nt * 8 + 2 * c;
        const float b0 = bias[v], b1 = bias[v + 1];
#pragma unroll
        for (int ma = 0; ma < 2; ma++)
#pragma unroll
            for (int hh = 0; hh < 2; hh++) {
                const size_t rg = (size_t)bx * 128 + wm * 32 + ma * 16 + g + hh * 8;
                float2 r;
                r.x = acc[ma][nt][hh * 2 + 0] + b0;
                r.y = acc[ma][nt][hh * 2 + 1] + b1;
                *(float2*)&g_gi0[rg * G_ + v] = r;
            }
    }
}

// ---- vocab projection (2 steps per M-tile) ----
__global__ void __launch_bounds__(256) out_mma(const float* __restrict__ bout,
                                               float* __restrict__ out)
{
    __shared__ unsigned sA[2][128 * AST2];
    __shared__ unsigned sB[2][128 * AST2];
    const int bx = blockIdx.x;
    const int n0 = blockIdx.y * 128;
    const int tid = threadIdx.x, w = tid >> 5, lane = tid & 31;
    const int wm = w & 3, wn = w >> 2, g = lane >> 2, c = lane & 3;

    float acc[2][8][4];
#pragma unroll
    for (int ma = 0; ma < 2; ma++)
#pragma unroll
        for (int i = 0; i < 8; i++)
#pragma unroll
            for (int j = 0; j < 4; j++) acc[ma][i][j] = 0.0f;

    big_tile_mainloop(g_top_hi + (size_t)bx * 128 * H_, g_top_lo + (size_t)bx * 128 * H_,
                      g_wout_hi, g_wout_lo, n0, sA, sB, acc, tid, wm, wn);

#pragma unroll
    for (int nt = 0; nt < 8; nt++) {
        const int v = n0 + wn * 64 + nt * 8 + 2 * c;
        const float b0 = __ldg(bout + v), b1 = __ldg(bout + v + 1);
#pragma unroll
        for (int ma = 0; ma < 2; ma++)
#pragma unroll
            for (int hh = 0; hh < 2; hh++) {
                const int rg = bx * 128 + wm * 32 + ma * 16 + g + hh * 8;
                const int s = rg >> 6, b = rg & 63;
                if (s < T_ - 1) {
                    float2 r;
                    r.x = acc[ma][nt][hh * 2 + 0] + b0;
                    r.y = acc[ma][nt][hh * 2 + 1] + b1;
                    *(float2*)&out[(size_t)b * (T_ * V_) + (size_t)(s + 1) * V_ + v] = r;
                }
            }
    }
}

// ================= recurrent GEMM pass (A loads L2-coherent) =================
__device__ __forceinline__ void gru_pass2(
    const bf16* __restrict__ Ahi, const bf16* __restrict__ Alo,
    const bf16* __restrict__ Whi, const bf16* __restrict__ Wlo,
    int j0, int kbase, int nchunks,
    unsigned* sA0, unsigned* sA1, unsigned* sW0, unsigned* sW1,
    float (&acc)[3][4], int tg, int m0)
{
    const int lane = tg & 31;
    const int mi = lane >> 3, ri = lane & 7;

    const unsigned sA0b = (unsigned)__cvta_generic_to_shared(sA0);
    const unsigned sA1b = (unsigned)__cvta_generic_to_shared(sA1);
    const unsigned sW0b = (unsigned)__cvta_generic_to_shared(sW0);
    const unsigned sW1b = (unsigned)__cvta_generic_to_shared(sW1);

    const unsigned aoff  = ((m0 + ri + (mi & 1) * 8) * ASTR + (mi >> 1) * 4) * 4;
    const unsigned w4off = ((ri + (mi >> 1) * 8) * ASTR + (mi & 1) * 4) * 4;
    const unsigned w2off = ((16 + ri) * ASTR + ((lane >> 3) & 1) * 4) * 4;

    int4 pa[8], pw[3];
    auto ld = [&](int k0) {
#pragma unroll
        for (int it = 0; it < 8; it++) {
            const int idx = tg + it * 128;
            const int pl = idx >> 9;
            const int rem = idx & 511;
            const int r = rem >> 3, q = rem & 7;
            // h/xl are mutated across grid barriers inside one launch: L1 can be
            // stale -> L2-coherent load (bypass L1).
            pa[it] = __ldcg((const int4*)((pl ? Alo : Ahi) + (size_t)r * H_ + k0 + q * 8));
        }
#pragma unroll
        for (int it = 0; it < 3; it++) {
            const int idx = tg + it * 128;
            const int pl = (idx >= 192) ? 1 : 0;
            const int i = idx - 192 * pl;
            const int r = i >> 3, q = i & 7;
            const int grow = (r >> 3) * H_ + j0 + (r & 7);
            pw[it] = *(const int4*)((pl ? Wlo : Whi) + (size_t)grow * H_ + k0 + q * 8);
        }
    };
    auto st = [&]() {
#pragma unroll
        for (int it = 0; it < 8; it++) {
            const int idx = tg + it * 128;
            const int pl = idx >> 9;
            const int rem = idx & 511;
            const int r = rem >> 3, q = rem & 7;
            *(int4*)&((pl ? sA1 : sA0)[r * ASTR + q * 4]) = pa[it];
        }
#pragma unroll
        for (int it = 0; it < 3; it++) {
            const int idx = tg + it * 128;
            const int pl = (idx >= 192) ? 1 : 0;
            const int i = idx - 192 * pl;
            const int r = i >> 3, q = i & 7;
            *(int4*)&((pl ? sW1 : sW0)[r * ASTR + q * 4]) = pw[it];
        }
    };

    ld(kbase);
    for (int ch = 0; ch < nchunks; ch++) {
        st();
        __syncthreads();
        if (ch + 1 < nchunks) ld(kbase + (ch + 1) * 64);
#pragma unroll
        for (int ks = 0; ks < 4; ks++) {
            const unsigned kb = ks * 32;
            unsigned ah0, ah1, ah2, ah3, al0, al1, al2, al3;
            ldsm_x4(ah0, ah1, ah2, ah3, sA0b + aoff + kb);
            ldsm_x4(al0, al1, al2, al3, sA1b + aoff + kb);
            unsigned bh0, bh1, bh2, bh3, bl0, bl1, bl2, bl3;
            unsigned ch0, ch1, cl0, cl1;
            ldsm_x4(bh0, bh1, bh2, bh3, sW0b + w4off + kb);
            ldsm_x4(bl0, bl1, bl2, bl3, sW1b + w4off + kb);
            ldsm_x2(ch0, ch1, sW0b + w2off + kb);
            ldsm_x2(cl0, cl1, sW1b + w2off + kb);
            mma_acc(acc[0], ah0, ah1, ah2, ah3, bh0, bh1);
            mma_acc(acc[1], ah0, ah1, ah2, ah3, bh2, bh3);
            mma_acc(acc[2], ah0, ah1, ah2, ah3, ch0, ch1);
            mma_acc(acc[0], ah0, ah1, ah2, ah3, bl0, bl1);
            mma_acc(acc[1], ah0, ah1, ah2, ah3, bl2, bl3);
            mma_acc(acc[2], ah0, ah1, ah2, ah3, cl0, cl1);
            mma_acc(acc[0], al0, al1, al2, al3, bh0, bh1);
            mma_acc(acc[1], al0, al1, al2, al3, bh2, bh3);
            mma_acc(acc[2], al0, al1, al2, al3, ch0, ch1);
        }
        __syncthreads();
    }
}

// C dump layout: C[b*25 + gate*8 + jj]
__device__ __forceinline__ void dump_frag(float* C, float (&acc)[3][4], int m0, int g, int c) {
#pragma unroll
    for (int nt = 0; nt < 3; nt++)
#pragma unroll
        for (int v = 0; v < 4; v++) {
            const int b = m0 + g + ((v >> 1) << 3);
            const int jj = 2 * c + (v & 1);
            C[b * 25 + nt * 8 + jj] = acc[nt][v];
        }
}

// ================= persistent recurrence: all 127 steps, one launch ==========
__global__ void __launch_bounds__(512) gru_persist(
    const float* __restrict__ bhh_e0, const float* __restrict__ bih_e1,
    const float* __restrict__ bhh_e1,
    const float* __restrict__ bhh_d0, const float* __restrict__ bih_d1,
    const float* __restrict__ bhh_d1,
    const int* __restrict__ src_lengths)
{
    extern __shared__ unsigned smem_u[];
    const int tid = threadIdx.x;
    const int grp = tid >> 7;              // 0..3
    const int tg = tid & 127;
    const int w2 = tg >> 5, lane = tid & 31;
    const int g = lane >> 2, c = lane & 3, m0 = w2 * 16;
    const int j0 = blockIdx.x * 8;
    const int nb = gridDim.x;

    unsigned* gbase = smem_u + grp * GRP_WORDS;
    unsigned* sA0 = gbase;
    unsigned* sA1 = gbase + SA_SZ;
    unsigned* sW0 = gbase + 2 * SA_SZ;
    unsigned* sW1 = gbase + 2 * SA_SZ + SW_SZ;
    float* C = (float*)(smem_u + 4 * GRP_WORDS);

    unsigned bar_no = 0;

    for (int st = 0; st < NSTEP; st++) {
        const bool enc = (st < S_);
        const int par = st & 1;

        // ---------- layer 0: gh = h0 @ Whh0^T, 4-way k-split ----------
        {
            const size_t woff = enc ? (size_t)0 : 3 * GH_;
            const float* bhh = enc ? bhh_e0 : bhh_d0;

            float acc[3][4];
#pragma unroll
            for (int i = 0; i < 3; i++)
#pragma unroll
                for (int j = 0; j < 4; j++) acc[i][j] = 0.0f;

            gru_pass2(g_h_hi[0][par], g_h_lo[0][par], g_wr_hi + woff, g_wr_lo + woff,
                      j0, grp * 256, 4, sA0, sA1, sW0, sW1, acc, tg, m0);

            if (grp > 0) dump_frag(C + (grp - 1) * 1600, acc, m0, g, c);
            __syncthreads();

            if (grp == 0) {
                const float* hf = g_hf[0][par];
                float* hfn = g_hf[0][par ^ 1];
#pragma unroll
                for (int v = 0; v < 4; v++) {
                    const int b = m0 + g + ((v >> 1) << 3);
                    const int jj = 2 * c + (v & 1);
                    const int j = j0 + jj;
                    const float a_r = acc[0][v] + C[b * 25 + jj]      + C[1600 + b * 25 + jj]      + C[3200 + b * 25 + jj];
                    const float a_z = acc[1][v] + C[b * 25 + 8 + jj]  + C[1600 + b * 25 + 8 + jj]  + C[3200 + b * 25 + 8 + jj];
                    const float a_n = acc[2][v] + C[b * 25 + 16 + jj] + C[1600 + b * 25 + 16 + jj] + C[3200 + b * 25 + 16 + jj];
                    const size_t gb = ((size_t)st * B_ + b) * G_;
                    const float r = sigm(g_gi0[gb + j] + a_r + bhh[j]);
                    const float z = sigm(g_gi0[gb + H_ + j] + a_z + bhh[H_ + j]);
                    const float n = tanhf(g_gi0[gb + 2 * H_ + j] + r * (a_n + bhh[2 * H_ + j]));
                    const float hprev = __ldcg(&hf[b * H_ + j]);
                    const float hnew = (1.0f - z) * n + z * hprev;
                    bf16 xh, xl; split2(hnew, xh, xl);
                    g_xl_hi[b * H_ + j] = xh; g_xl_lo[b * H_ + j] = xl;
                    float hs = hnew;
                    if (enc && st >= src_lengths[b]) hs = hprev;
                    hfn[b * H_ + j] = hs;
                    bf16 sh, sl; split2(hs, sh, sl);
                    g_h_hi[0][par ^ 1][b * H_ + j] = sh;
                    g_h_lo[0][par ^ 1][b * H_ + j] = sl;
                }
            }
        }
        grid_barrier(bar_no, nb);

        // ---------- layer 1: (gi, gh) x (2 k-halves) over 4 groups ----------
        {
            const size_t woffi = enc ? 2 * GH_ : 5 * GH_;
            const size_t woffh = enc ? 1 * GH_ : 4 * GH_;
            const float* bih = enc ? bih_e1 : bih_d1;
            const float* bhh = enc ? bhh_e1 : bhh_d1;

            const bf16 *Ahi, *Alo, *Whi, *Wlo;
            if (grp < 2) {
                Ahi = g_xl_hi; Alo = g_xl_lo;
                Whi = g_wr_hi + woffi; Wlo = g_wr_lo + woffi;
            } else {
                Ahi = g_h_hi[1][par]; Alo = g_h_lo[1][par];
                Whi = g_wr_hi + woffh; Wlo = g_wr_lo + woffh;
            }
            const int kbase = (grp & 1) * 512;

            float acc[3][4];
#pragma unroll
            for (int i = 0; i < 3; i++)
#pragma unroll
                for (int j = 0; j < 4; j++) acc[i][j] = 0.0f;

            gru_pass2(Ahi, Alo, Whi, Wlo, j0, kbase, 8, sA0, sA1, sW0, sW1, acc, tg, m0);

            if (grp > 0) dump_frag(C + (grp - 1) * 1600, acc, m0, g, c);
            __syncthreads();

            if (grp == 0) {
                const float* hf = g_hf[1][par];
                float* hfn = g_hf[1][par ^ 1];
#pragma unroll
                for (int v = 0; v < 4; v++) {
                    const int b = m0 + g + ((v >> 1) << 3);
                    const int jj = 2 * c + (v & 1);
                    const int j = j0 + jj;
                    const float gir = acc[0][v] + C[b * 25 + jj];
                    const float giz = acc[1][v] + C[b * 25 + 8 + jj];
                    const float gin = acc[2][v] + C[b * 25 + 16 + jj];
                    const float ghr = C[1600 + b * 25 + jj]      + C[3200 + b * 25 + jj];
                    const float ghz = C[1600 + b * 25 + 8 + jj]  + C[3200 + b * 25 + 8 + jj];
                    const float ghn = C[1600 + b * 25 + 16 + jj] + C[3200 + b * 25 + 16 + jj];
                    const float r = sigm(gir + bih[j] + ghr + bhh[j]);
                    const float z = sigm(giz + bih[H_ + j] + ghz + bhh[H_ + j]);
                    const float n = tanhf(gin + bih[2 * H_ + j] + r * (ghn + bhh[2 * H_ + j]));
                    const float hprev = __ldcg(&hf[b * H_ + j]);
                    const float hnew = (1.0f - z) * n + z * hprev;
                    if (!enc) {
                        const int step = st - S_;
                        bf16 th, tl; split2(hnew, th, tl);
                        g_top_hi[((size_t)step * B_ + b) * H_ + j] = th;
                        g_top_lo[((size_t)step * B_ + b) * H_ + j] = tl;
                    }
                    float hs = hnew;
                    if (enc && st >= src_lengths[b]) hs = hprev;
                    hfn[b * H_ + j] = hs;
                    bf16 sh, sl; split2(hs, sh, sl);
                    g_h_hi[1][par ^ 1][b * H_ + j] = sh;
                    g_h_lo[1][par ^ 1][b * H_ + j] = sl;
                }
            }
        }
        grid_barrier(bar_no, nb);
    }
}

// ------------------------------- host driver ---------------------------------
extern "C" void kernel_launch(void* const* d_in, const int* in_sizes, int n_in,
                              void* d_out, int out_size) {
    (void)in_sizes; (void)n_in; (void)out_size;
    const int*   src_tokens  = (const int*)d_in[0];
    const int*   src_lengths = (const int*)d_in[1];
    const int*   trg         = (const int*)d_in[2];
    const float* emb_enc = (const float*)d_in[3];
    const float* Wih_enc = (const float*)d_in[4];
    const float* Whh_enc = (const float*)d_in[5];
    const float* bih_enc = (const float*)d_in[6];
    const float* bhh_enc = (const float*)d_in[7];
    const float* emb_dec = (const float*)d_in[8];
    const float* Wih_dec = (const float*)d_in[9];
    const float* Whh_dec = (const float*)d_in[10];
    const float* bih_dec = (const float*)d_in[11];
    const float* bhh_dec = (const float*)d_in[12];
    const float* Wout    = (const float*)d_in[13];
    const float* bout    = (const float*)d_in[14];
    float* out = (float*)d_out;

    cudaFuncSetAttribute(gru_persist, cudaFuncAttributeMaxDynamicSharedMemorySize, GRU_SMEM_BYTES);

    init_kernel<<<512, 256>>>(out);
    split_all<<<dim3(512, 9), 256>>>(Whh_enc, Whh_enc + GH_, Wih_enc + GH_,
                                     Whh_dec, Whh_dec + GH_, Wih_dec + GH_,
                                     Wih_enc, Wih_dec, Wout);
    gather_all<<<2048, 256>>>(src_tokens, trg, emb_enc, emb_dec);
    gi0_all<<<dim3(64, G_ / 128), 256>>>(bih_enc, bih_dec);

    // entire recurrence: ONE launch, 128 co-resident CTAs, software grid barriers
    gru_persist<<<H_ / 8, 512, GRU_SMEM_BYTES>>>(
        bhh_enc, bih_enc + G_, bhh_enc + G_,
        bhh_dec, bih_dec + G_, bhh_dec + G_,
        src_lengths);

    out_mma<<<dim3(32, V_ / 128), 256>>>(bout, out);
}